// round 4
// baseline (speedup 1.0000x reference)
#include <cuda_runtime.h>
#include <cuda_fp16.h>
#include <math.h>
#include <stdint.h>

#define NN    30000
#define EE    480000
#define HIDN  256
#define NLAY  6

// ---------------- static device scratch ----------------
static __device__ __align__(128) __half g_hh[2][NN * HIDN];   // h split hi (fp16)
static __device__ __align__(128) __half g_hl[2][NN * HIDN];   // h split lo (fp16)
static __device__ __align__(128) float  g_xl[NN * HIDN];
static __device__ __align__(128) float  g_xr[NN * HIDN];
static __device__ __align__(128) float  g_t[NN * 128];
static __device__ __align__(128) __half g_WTh[(NLAY * 512 + 128) * 256];
static __device__ __align__(128) __half g_WTl[(NLAY * 512 + 128) * 256];
static __device__ __align__(128) float  g_B[NLAY * 10 * 256];
static __device__ __align__(128) float  g_c[NLAY * 256];
static __device__ __align__(128) float  g_A[NLAY * 10 * 256];
static __device__ __align__(128) float  g_d[NLAY * 256];
static __device__ int g_cnt[NN + 1];
static __device__ int g_start[NN + 1];
static __device__ int g_cursor[NN + 1];
static __device__ int g_eid[EE];

// ---------------- helpers ----------------
__device__ __forceinline__ void split_f16(float x, __half& hi, __half& lo) {
    hi = __float2half_rn(x);
    lo = __float2half_rn(x - __half2float(hi));
}

__device__ __forceinline__ uint32_t smem_u32(const void* p) {
    uint32_t a;
    asm("{ .reg .u64 t; cvta.to.shared.u64 t, %1; cvt.u32.u64 %0, t; }" : "=r"(a) : "l"(p));
    return a;
}

__device__ __forceinline__ void cp16(uint32_t dst, const void* src, int bytes) {
    asm volatile("cp.async.cg.shared.global [%0], [%1], 16, %2;"
                 :: "r"(dst), "l"(src), "r"(bytes));
}
__device__ __forceinline__ void cp_commit() {
    asm volatile("cp.async.commit_group;" ::: "memory");
}

__device__ __forceinline__ void mma_f16(float* d, const uint32_t* a, const uint32_t* b) {
    asm volatile(
        "mma.sync.aligned.m16n8k16.row.col.f32.f16.f16.f32 "
        "{%0,%1,%2,%3}, {%4,%5,%6,%7}, {%8,%9}, {%0,%1,%2,%3};"
        : "+f"(d[0]), "+f"(d[1]), "+f"(d[2]), "+f"(d[3])
        : "r"(a[0]), "r"(a[1]), "r"(a[2]), "r"(a[3]), "r"(b[0]), "r"(b[1]));
}

// ---------------- CSR build ----------------
__global__ void zero_kernel() {
    int i = blockIdx.x * 256 + threadIdx.x;
    if (i <= NN) g_cnt[i] = 0;
}
__global__ void count_kernel(const int* __restrict__ dst) {
    int e = blockIdx.x * 256 + threadIdx.x;
    if (e < EE) atomicAdd(&g_cnt[dst[e]], 1);
}
__global__ void scan_kernel() {
    __shared__ int part[1024];
    const int T = 1024, ITEMS = (NN + T - 1) / T;
    int tid = threadIdx.x, base = tid * ITEMS, s = 0;
    for (int i = 0; i < ITEMS; ++i) { int idx = base + i; if (idx < NN) s += g_cnt[idx]; }
    part[tid] = s;
    __syncthreads();
    for (int off = 1; off < T; off <<= 1) {
        int v = 0;
        if (tid >= off) v = part[tid - off];
        __syncthreads();
        part[tid] += v;
        __syncthreads();
    }
    int run = (tid == 0) ? 0 : part[tid - 1];
    for (int i = 0; i < ITEMS; ++i) {
        int idx = base + i;
        if (idx < NN) { g_start[idx] = run; g_cursor[idx] = run; run += g_cnt[idx]; }
    }
    if (tid == T - 1) g_start[NN] = part[T - 1];
}
__global__ void fill_kernel(const int* __restrict__ dst) {
    int e = blockIdx.x * 256 + threadIdx.x;
    if (e < EE) { int pos = atomicAdd(&g_cursor[dst[e]], 1); g_eid[pos] = e; }
}
// deterministic order: sort each node's list in a local buffer (L1), not global
__global__ void sort_kernel() {
    int n = blockIdx.x * 128 + threadIdx.x;
    if (n >= NN) return;
    int s0 = g_start[n], s1 = g_start[n + 1];
    int d = s1 - s0;
    if (d <= 1) return;
    if (d <= 96) {
        int buf[96];
        for (int i = 0; i < d; ++i) buf[i] = g_eid[s0 + i];
        for (int i = 1; i < d; ++i) {
            int v = buf[i], j = i - 1;
            while (j >= 0 && buf[j] > v) { buf[j + 1] = buf[j]; --j; }
            buf[j + 1] = v;
        }
        for (int i = 0; i < d; ++i) g_eid[s0 + i] = buf[i];
    } else {
        for (int i = s0 + 1; i < s1; ++i) {
            int v = g_eid[i], j = i - 1;
            while (j >= s0 && g_eid[j] > v) { g_eid[j + 1] = g_eid[j]; --j; }
            g_eid[j + 1] = v;
        }
    }
}

// ---------------- edge-matrix chain precompute ----------------
__global__ void chain_kernel(const float* __restrict__ eW, const float* __restrict__ eb,
                             const float* __restrict__ Weu, const float* __restrict__ beu) {
    __shared__ float Ash[10 * 256];
    __shared__ float dsh[256];
    int tid = threadIdx.x;
    for (int t = tid; t < 2560; t += 256) Ash[t] = eW[t];
    dsh[tid] = eb[tid];
    __syncthreads();
    for (int i = 0; i < NLAY; ++i) {
        for (int t = tid; t < 2560; t += 256) g_A[i * 2560 + t] = Ash[t];
        g_d[i * 256 + tid] = dsh[tid];
        __syncthreads();
        if (i == NLAY - 1) break;
        const float* Wp = Weu + (size_t)i * 65536;
        float accA[10];
        #pragma unroll
        for (int k = 0; k < 10; ++k) accA[k] = 0.f;
        float accd = 0.f;
        for (int c = 0; c < 256; ++c) {
            float w = Wp[c * 256 + tid];
            accd = fmaf(dsh[c], w, accd);
            #pragma unroll
            for (int k = 0; k < 10; ++k) accA[k] = fmaf(Ash[k * 256 + c], w, accA[k]);
        }
        accd += beu[i * 256 + tid];
        __syncthreads();
        #pragma unroll
        for (int k = 0; k < 10; ++k) Ash[k * 256 + tid] = accA[k];
        dsh[tid] = accd;
        __syncthreads();
    }
}
__global__ void bmat_kernel(const float* __restrict__ We) {
    __shared__ float Ash[10 * 256];
    __shared__ float dsh[256];
    int i = blockIdx.x, tid = threadIdx.x;
    for (int t = tid; t < 2560; t += 256) Ash[t] = g_A[i * 2560 + t];
    dsh[tid] = g_d[i * 256 + tid];
    __syncthreads();
    const float* Wp = We + (size_t)i * 65536;
    float accB[10];
    #pragma unroll
    for (int k = 0; k < 10; ++k) accB[k] = 0.f;
    float accc = 0.f;
    for (int c = 0; c < 256; ++c) {
        float w = Wp[c * 256 + tid];
        accc = fmaf(dsh[c], w, accc);
        #pragma unroll
        for (int k = 0; k < 10; ++k) accB[k] = fmaf(Ash[k * 256 + c], w, accB[k]);
    }
    #pragma unroll
    for (int k = 0; k < 10; ++k) g_B[i * 2560 + k * 256 + tid] = accB[k];
    g_c[i * 256 + tid] = accc;
}

// ---------------- weight transpose + fp16 split ----------------
__global__ void wprep_kernel(const float* __restrict__ Wl, const float* __restrict__ Wr,
                             const float* __restrict__ oW1) {
    int idx = blockIdx.x * 256 + threadIdx.x;
    const int LTOT = NLAY * 512 * 256;
    float v;
    if (idx < LTOT) {
        int l = idx >> 17;
        int rem = idx & 131071;
        int row = rem >> 8, k = rem & 255;
        v = (row < 256) ? Wl[(size_t)l * 65536 + k * 256 + row]
                        : Wr[(size_t)l * 65536 + k * 256 + (row - 256)];
    } else if (idx < LTOT + 128 * 256) {
        int rem = idx - LTOT;
        int row = rem >> 8, k = rem & 255;
        v = oW1[k * 128 + row];
    } else return;
    __half hi, lo;
    split_f16(v, hi, lo);
    g_WTh[idx] = hi; g_WTl[idx] = lo;
}

// ---------------- node encoder ----------------
__global__ void encoder_kernel(const float* __restrict__ x, const float* __restrict__ nW,
                               const float* __restrict__ nb) {
    int idx = blockIdx.x * 256 + threadIdx.x;
    int n = idx >> 8, c = idx & 255;
    if (n >= NN) return;
    float s = nb[c];
    #pragma unroll
    for (int k = 0; k < 13; ++k) s = fmaf(x[n * 13 + k], nW[k * 256 + c], s);
    __half hi, lo;
    split_f16(s, hi, lo);
    g_hh[0][idx] = hi; g_hl[0][idx] = lo;
}

// ---------------- 3xFP16 mma.sync GEMM, cp.async double-buffered ----------------
// C[128 x 128-col-block] = h[hsel] @ WT^T (+bias, leaky slope).
// 256 threads = 8 warps (2m x 4n), warp tile 64x32, mma m16n8k16, BK=32.
// smem per buffer: Ah|Al|Bh|Bl, each 128 rows x 40 halves (stride 40 -> conflict-free).
#define SA 40
#define ARR_H 5120                  // halves per array
#define BUF_H (4 * ARR_H)           // halves per buffer
#define GSMEM_BYTES (2 * BUF_H * 2) // 81920

__global__ __launch_bounds__(256, 2)
void mma_gemm(int hsel, int wrow0, const float* __restrict__ bias0,
              const float* __restrict__ bias1, int outmode, float slope) {
    extern __shared__ __align__(16) __half sm[];
    const __half* __restrict__ Ah = g_hh[hsel];
    const __half* __restrict__ Al = g_hl[hsel];

    int tid = threadIdx.x;
    int wid = tid >> 5, lane = tid & 31;
    int warp_m = wid & 1, warp_n = wid >> 1;
    int m0 = blockIdx.x * 128;
    int colg = blockIdx.y * 128;
    int tig = lane & 3, grp = lane >> 2;

    float c[4][4][4];
    #pragma unroll
    for (int mi = 0; mi < 4; ++mi)
        #pragma unroll
        for (int ni = 0; ni < 4; ++ni)
            #pragma unroll
            for (int j = 0; j < 4; ++j) c[mi][ni][j] = 0.f;

    // ---- async copy of one 32-k block into buffer buf ----
    auto issue = [&](int kb, int buf) {
        int kt = kb * 32;
        __half* base = sm + buf * BUF_H;
        #pragma unroll
        for (int i = 0; i < 8; ++i) {
            int slot = tid + i * 256;        // 0..2047
            int arr = slot >> 9;             // 0:Ah 1:Al 2:Bh 3:Bl
            int rc = slot & 511;
            int r = rc >> 2, ch = rc & 3;
            const __half* src;
            int bytes = 16;
            if (arr < 2) {
                int gm = m0 + r;
                if (gm >= NN) { gm = NN - 1; bytes = 0; }
                src = (arr == 0 ? Ah : Al) + (size_t)gm * 256 + kt + ch * 8;
            } else {
                int row = wrow0 + colg + r;
                src = (arr == 2 ? g_WTh : g_WTl) + (size_t)row * 256 + kt + ch * 8;
            }
            uint32_t dst = smem_u32(base + arr * ARR_H + r * SA + ch * 8);
            cp16(dst, src, bytes);
        }
        cp_commit();
    };

    issue(0, 0);
    for (int kb = 0; kb < 8; ++kb) {
        if (kb < 7) {
            issue(kb + 1, (kb + 1) & 1);
            asm volatile("cp.async.wait_group 1;" ::: "memory");
        } else {
            asm volatile("cp.async.wait_group 0;" ::: "memory");
        }
        __syncthreads();

        const __half* base = sm + (kb & 1) * BUF_H;
        const __half* Abh = base;
        const __half* Abl = base + ARR_H;
        const __half* Bbh = base + 2 * ARR_H;
        const __half* Bbl = base + 3 * ARR_H;

        #pragma unroll
        for (int ks = 0; ks < 2; ++ks) {
            int k0 = ks * 16;
            uint32_t bh[4][2], bl[4][2];
            #pragma unroll
            for (int ni = 0; ni < 4; ++ni) {
                int nb = (warp_n * 32 + ni * 8 + grp) * SA + k0 + tig * 2;
                bh[ni][0] = *(const uint32_t*)&Bbh[nb];
                bh[ni][1] = *(const uint32_t*)&Bbh[nb + 8];
                bl[ni][0] = *(const uint32_t*)&Bbl[nb];
                bl[ni][1] = *(const uint32_t*)&Bbl[nb + 8];
            }
            #pragma unroll
            for (int mi = 0; mi < 4; ++mi) {
                int ab = (warp_m * 64 + mi * 16 + grp) * SA + k0 + tig * 2;
                uint32_t ah[4], al[4];
                ah[0] = *(const uint32_t*)&Abh[ab];
                ah[1] = *(const uint32_t*)&Abh[ab + 8 * SA];
                ah[2] = *(const uint32_t*)&Abh[ab + 8];
                ah[3] = *(const uint32_t*)&Abh[ab + 8 * SA + 8];
                al[0] = *(const uint32_t*)&Abl[ab];
                al[1] = *(const uint32_t*)&Abl[ab + 8 * SA];
                al[2] = *(const uint32_t*)&Abl[ab + 8];
                al[3] = *(const uint32_t*)&Abl[ab + 8 * SA + 8];
                #pragma unroll
                for (int ni = 0; ni < 4; ++ni) {
                    mma_f16(c[mi][ni], ah, bh[ni]);
                    mma_f16(c[mi][ni], ah, bl[ni]);
                    mma_f16(c[mi][ni], al, bh[ni]);
                }
            }
        }
        __syncthreads();
    }

    // epilogue: bias + leaky, route to g_xl / g_xr / g_t
    #pragma unroll
    for (int mi = 0; mi < 4; ++mi) {
        #pragma unroll
        for (int ni = 0; ni < 4; ++ni) {
            int gn = colg + warp_n * 32 + ni * 8 + tig * 2;
            float* outp; const float* bp; int cc, ld;
            if (outmode)        { outp = g_t;  bp = bias0; cc = gn;       ld = 128; }
            else if (gn < 256)  { outp = g_xl; bp = bias0; cc = gn;       ld = 256; }
            else                { outp = g_xr; bp = bias1; cc = gn - 256; ld = 256; }
            float b0v = bp[cc], b1v = bp[cc + 1];
            int gm = m0 + warp_m * 64 + mi * 16 + grp;
            if (gm < NN) {
                float v0 = c[mi][ni][0] + b0v; v0 = v0 >= 0.f ? v0 : slope * v0;
                float v1 = c[mi][ni][1] + b1v; v1 = v1 >= 0.f ? v1 : slope * v1;
                *(float2*)(outp + (size_t)gm * ld + cc) = make_float2(v0, v1);
            }
            int gm2 = gm + 8;
            if (gm2 < NN) {
                float v0 = c[mi][ni][2] + b0v; v0 = v0 >= 0.f ? v0 : slope * v0;
                float v1 = c[mi][ni][3] + b1v; v1 = v1 >= 0.f ? v1 : slope * v1;
                *(float2*)(outp + (size_t)gm2 * ld + cc) = make_float2(v0, v1);
            }
        }
    }
}

// ---------------- fused GATv2 attention v2 ----------------
// 2 warps per destination node, 4 heads per warp; ep-matrix slice in registers;
// edge-attr via warp-uniform 64-bit loads; zero shared memory, zero barriers.
__global__ __launch_bounds__(256)
void attn_kernel(int layer, int hin,
                 const float* __restrict__ att, const float* __restrict__ conv_b,
                 const float* __restrict__ bng, const float* __restrict__ bnb,
                 const float* __restrict__ bnrm, const float* __restrict__ bnrv,
                 const int* __restrict__ src_arr,
                 const float* __restrict__ eattr) {
    int tid = threadIdx.x;
    int warp = tid >> 5, lane = tid & 31;
    int n = blockIdx.x * 4 + (warp >> 1);
    int hh = warp & 1;
    int cbase = hh * 128;
    int hout = hin ^ 1;

    // per-lane parameters in registers
    float Brg[10][4];
    #pragma unroll
    for (int k = 0; k < 10; ++k)
        #pragma unroll
        for (int h = 0; h < 4; ++h)
            Brg[k][h] = g_B[layer * 2560 + k * 256 + cbase + h * 32 + lane];
    float creg[4], attr[4], cbr[4], scr[4], shr[4], xr4[4];
    #pragma unroll
    for (int h = 0; h < 4; ++h) {
        int ch = cbase + h * 32 + lane;
        creg[h] = g_c[layer * 256 + ch];
        attr[h] = att[layer * 256 + ch];
        cbr[h]  = conv_b[layer * 256 + ch];
        float sc = bng[layer * 256 + ch] * rsqrtf(bnrv[layer * 256 + ch] + 1e-5f);
        scr[h] = sc;
        shr[h] = bnb[layer * 256 + ch] - bnrm[layer * 256 + ch] * sc;
        xr4[h] = g_xr[(size_t)n * 256 + ch];
    }

    float mh[4], ssum[4], accv[4];
    #pragma unroll
    for (int h = 0; h < 4; ++h) { mh[h] = -INFINITY; ssum[h] = 0.f; accv[h] = 0.f; }

    int s0 = g_start[n], s1 = g_start[n + 1];
    for (int p = s0; p < s1; ++p) {
        int e = g_eid[p];
        int sn = src_arr[e];
        // warp-uniform edge attributes (L1 broadcast, 8-byte aligned)
        const float2* ep2 = (const float2*)(eattr + (size_t)e * 10);
        float2 ea0 = ep2[0], ea1 = ep2[1], ea2 = ep2[2], ea3 = ep2[3], ea4 = ep2[4];
        float ea[10] = {ea0.x, ea0.y, ea1.x, ea1.y, ea2.x, ea2.y, ea3.x, ea3.y, ea4.x, ea4.y};

        float xls[4], val[4];
        #pragma unroll
        for (int h = 0; h < 4; ++h) {
            xls[h] = g_xl[(size_t)sn * 256 + cbase + h * 32 + lane];
            val[h] = creg[h];
        }
        #pragma unroll
        for (int k = 0; k < 10; ++k)
            #pragma unroll
            for (int h = 0; h < 4; ++h)
                val[h] = fmaf(ea[k], Brg[k][h], val[h]);
        #pragma unroll
        for (int h = 0; h < 4; ++h) {
            float v = xls[h] + xr4[h] + val[h];
            v = v >= 0.f ? v : 0.2f * v;        // leaky 0.2
            val[h] = v * attr[h];
        }
        #pragma unroll
        for (int off = 16; off > 0; off >>= 1) {
            #pragma unroll
            for (int h = 0; h < 4; ++h)
                val[h] += __shfl_xor_sync(0xffffffffu, val[h], off);
        }
        #pragma unroll
        for (int h = 0; h < 4; ++h) {
            float L = val[h];
            float nm = fmaxf(mh[h], L);
            float f = __expf(mh[h] - nm);
            float w = __expf(L - nm);
            ssum[h] = ssum[h] * f + w;
            accv[h] = accv[h] * f + w * xls[h];
            mh[h] = nm;
        }
    }

    #pragma unroll
    for (int h = 0; h < 4; ++h) {
        int ch = cbase + h * 32 + lane;
        size_t idx = (size_t)n * 256 + ch;
        float agg = accv[h] / (ssum[h] + 1e-16f);
        float v = agg + cbr[h];
        v = v * scr[h] + shr[h];                // BN (eval)
        v = v >= 0.f ? v : 0.01f * v;           // leaky 0.01
        if (layer >= 1)
            v += __half2float(g_hh[hin][idx]) + __half2float(g_hl[hin][idx]);
        __half hi, lo;
        split_f16(v, hi, lo);
        g_hh[hout][idx] = hi;
        g_hl[hout][idx] = lo;
    }
}

// ---------------- head: out = t @ W2 + b2 ----------------
__global__ void head2_kernel(const float* __restrict__ W2, const float* __restrict__ b2,
                             float* __restrict__ out) {
    __shared__ float w[128];
    int tid = threadIdx.x;
    if (tid < 128) w[tid] = W2[tid];
    __syncthreads();
    int n = blockIdx.x * 256 + tid;
    if (n >= NN) return;
    float s = b2[0];
    const float* tp = g_t + (size_t)n * 128;
    #pragma unroll
    for (int j = 0; j < 128; ++j) s = fmaf(tp[j], w[j], s);
    out[n] = s;
}

// ---------------- launch ----------------
extern "C" void kernel_launch(void* const* d_in, const int* in_sizes, int n_in,
                              void* d_out, int out_size) {
    const float* x      = (const float*)d_in[0];
    const int*   ei     = (const int*)d_in[1];
    const float* eattr  = (const float*)d_in[2];
    const float* nW     = (const float*)d_in[3];
    const float* nb     = (const float*)d_in[4];
    const float* eW     = (const float*)d_in[5];
    const float* eb     = (const float*)d_in[6];
    const float* Wl     = (const float*)d_in[7];
    const float* bl     = (const float*)d_in[8];
    const float* Wr     = (const float*)d_in[9];
    const float* br     = (const float*)d_in[10];
    const float* We     = (const float*)d_in[11];
    const float* att    = (const float*)d_in[12];
    const float* conv_b = (const float*)d_in[13];
    const float* Weu    = (const float*)d_in[14];
    const float* beu    = (const float*)d_in[15];
    const float* bng    = (const float*)d_in[16];
    const float* bnb    = (const float*)d_in[17];
    const float* bnrm   = (const float*)d_in[18];
    const float* bnrv   = (const float*)d_in[19];
    const float* oW1    = (const float*)d_in[20];
    const float* ob1    = (const float*)d_in[21];
    const float* oW2    = (const float*)d_in[22];
    const float* ob2    = (const float*)d_in[23];

    const int* srcp = ei;
    const int* dstp = ei + EE;

    static int attr_set = 0;
    if (!attr_set) {
        cudaFuncSetAttribute(mma_gemm, cudaFuncAttributeMaxDynamicSharedMemorySize,
                             GSMEM_BYTES);
        attr_set = 1;
    }

    // CSR build (deterministic)
    zero_kernel<<<(NN + 256) / 256, 256>>>();
    count_kernel<<<(EE + 255) / 256, 256>>>(dstp);
    scan_kernel<<<1, 1024>>>();
    fill_kernel<<<(EE + 255) / 256, 256>>>(dstp);
    sort_kernel<<<(NN + 127) / 128, 128>>>();

    // edge matrix chain + weight prep
    chain_kernel<<<1, 256>>>(eW, eb, Weu, beu);
    bmat_kernel<<<NLAY, 256>>>(We);
    wprep_kernel<<<3200, 256>>>(Wl, Wr, oW1);

    // node encoder
    encoder_kernel<<<NN, 256>>>(x, nW, nb);

    const int MT = (NN + 127) / 128;   // 235
    dim3 gemm_grid(MT, 4);
    dim3 head_grid(MT, 1);
    int cur = 0;
    for (int i = 0; i < NLAY; ++i) {
        mma_gemm<<<gemm_grid, 256, GSMEM_BYTES>>>(cur, i * 512, bl + i * 256, br + i * 256,
                                                  /*outmode=*/0, /*slope=*/1.0f);
        attn_kernel<<<NN / 4, 256>>>(i, cur, att, conv_b, bng, bnb, bnrm, bnrv,
                                     srcp, eattr);
        cur ^= 1;
    }

    // output head
    mma_gemm<<<head_grid, 256, GSMEM_BYTES>>>(cur, NLAY * 512, ob1, (const float*)0,
                                              /*outmode=*/1, /*slope=*/0.01f);
    head2_kernel<<<(NN + 255) / 256, 256>>>(oW2, ob2, (float*)d_out);
}

// round 5
// speedup vs baseline: 1.7619x; 1.7619x over previous
#include <cuda_runtime.h>
#include <cuda_fp16.h>
#include <math.h>
#include <stdint.h>

#define NN    30000
#define EE    480000
#define HIDN  256
#define NLAY  6

// ---------------- static device scratch ----------------
static __device__ __align__(128) __half g_hh[2][NN * HIDN];   // h split hi (fp16)
static __device__ __align__(128) __half g_hl[2][NN * HIDN];   // h split lo (fp16)
static __device__ __align__(128) float  g_xl[NN * HIDN];
static __device__ __align__(128) float  g_xr[NN * HIDN];
static __device__ __align__(128) float  g_t[NN * 128];
static __device__ __align__(128) __half g_WTh[(NLAY * 512 + 128) * 256];
static __device__ __align__(128) __half g_WTl[(NLAY * 512 + 128) * 256];
static __device__ __align__(128) float  g_B[NLAY * 10 * 256];
static __device__ __align__(128) float  g_c[NLAY * 256];
static __device__ __align__(128) float  g_A[NLAY * 10 * 256];
static __device__ __align__(128) float  g_d[NLAY * 256];
static __device__ int g_cnt[NN + 1];
static __device__ int g_start[NN + 1];
static __device__ int g_cursor[NN + 1];
static __device__ int g_eid[EE];
// dst-sorted edge data (built once)
static __device__ __align__(128) int   g_srcs[EE];
static __device__ __align__(128) int   g_dsts[EE];
static __device__ __align__(128) float g_eas[EE * 10];
// per-layer per-edge exp(logit) [p][h]
static __device__ __align__(128) float g_expw[EE * 8];

// ---------------- helpers ----------------
__device__ __forceinline__ void split_f16(float x, __half& hi, __half& lo) {
    hi = __float2half_rn(x);
    lo = __float2half_rn(x - __half2float(hi));
}

__device__ __forceinline__ uint32_t smem_u32(const void* p) {
    uint32_t a;
    asm("{ .reg .u64 t; cvta.to.shared.u64 t, %1; cvt.u32.u64 %0, t; }" : "=r"(a) : "l"(p));
    return a;
}

__device__ __forceinline__ void cp16(uint32_t dst, const void* src, int bytes) {
    asm volatile("cp.async.cg.shared.global [%0], [%1], 16, %2;"
                 :: "r"(dst), "l"(src), "r"(bytes));
}
__device__ __forceinline__ void cp_commit() {
    asm volatile("cp.async.commit_group;" ::: "memory");
}

__device__ __forceinline__ void mma_f16(float* d, const uint32_t* a, const uint32_t* b) {
    asm volatile(
        "mma.sync.aligned.m16n8k16.row.col.f32.f16.f16.f32 "
        "{%0,%1,%2,%3}, {%4,%5,%6,%7}, {%8,%9}, {%0,%1,%2,%3};"
        : "+f"(d[0]), "+f"(d[1]), "+f"(d[2]), "+f"(d[3])
        : "r"(a[0]), "r"(a[1]), "r"(a[2]), "r"(a[3]), "r"(b[0]), "r"(b[1]));
}

// ---------------- CSR build ----------------
__global__ void zero_kernel() {
    int i = blockIdx.x * 256 + threadIdx.x;
    if (i <= NN) g_cnt[i] = 0;
}
__global__ void count_kernel(const int* __restrict__ dst) {
    int e = blockIdx.x * 256 + threadIdx.x;
    if (e < EE) atomicAdd(&g_cnt[dst[e]], 1);
}
__global__ void scan_kernel() {
    __shared__ int part[1024];
    const int T = 1024, ITEMS = (NN + T - 1) / T;
    int tid = threadIdx.x, base = tid * ITEMS, s = 0;
    for (int i = 0; i < ITEMS; ++i) { int idx = base + i; if (idx < NN) s += g_cnt[idx]; }
    part[tid] = s;
    __syncthreads();
    for (int off = 1; off < T; off <<= 1) {
        int v = 0;
        if (tid >= off) v = part[tid - off];
        __syncthreads();
        part[tid] += v;
        __syncthreads();
    }
    int run = (tid == 0) ? 0 : part[tid - 1];
    for (int i = 0; i < ITEMS; ++i) {
        int idx = base + i;
        if (idx < NN) { g_start[idx] = run; g_cursor[idx] = run; run += g_cnt[idx]; }
    }
    if (tid == T - 1) g_start[NN] = part[T - 1];
}
__global__ void fill_kernel(const int* __restrict__ dst) {
    int e = blockIdx.x * 256 + threadIdx.x;
    if (e < EE) { int pos = atomicAdd(&g_cursor[dst[e]], 1); g_eid[pos] = e; }
}
// deterministic order: sort each node's list in a local buffer
__global__ void sort_kernel() {
    int n = blockIdx.x * 128 + threadIdx.x;
    if (n >= NN) return;
    int s0 = g_start[n], s1 = g_start[n + 1];
    int d = s1 - s0;
    if (d <= 1) return;
    if (d <= 96) {
        int buf[96];
        for (int i = 0; i < d; ++i) buf[i] = g_eid[s0 + i];
        for (int i = 1; i < d; ++i) {
            int v = buf[i], j = i - 1;
            while (j >= 0 && buf[j] > v) { buf[j + 1] = buf[j]; --j; }
            buf[j + 1] = v;
        }
        for (int i = 0; i < d; ++i) g_eid[s0 + i] = buf[i];
    } else {
        for (int i = s0 + 1; i < s1; ++i) {
            int v = g_eid[i], j = i - 1;
            while (j >= s0 && g_eid[j] > v) { g_eid[j + 1] = g_eid[j]; --j; }
            g_eid[j + 1] = v;
        }
    }
}
// materialize dst-sorted edge arrays (once)
__global__ void gather_kernel(const int* __restrict__ src, const int* __restrict__ dst,
                              const float* __restrict__ eattr) {
    int p = blockIdx.x * 256 + threadIdx.x;
    if (p >= EE) return;
    int e = g_eid[p];
    g_srcs[p] = src[e];
    g_dsts[p] = dst[e];
    const float* s = eattr + (size_t)e * 10;
    float* d = g_eas + (size_t)p * 10;
    #pragma unroll
    for (int j = 0; j < 10; ++j) d[j] = s[j];
}

// ---------------- edge-matrix chain precompute ----------------
__global__ void chain_kernel(const float* __restrict__ eW, const float* __restrict__ eb,
                             const float* __restrict__ Weu, const float* __restrict__ beu) {
    __shared__ float Ash[10 * 256];
    __shared__ float dsh[256];
    int tid = threadIdx.x;
    for (int t = tid; t < 2560; t += 256) Ash[t] = eW[t];
    dsh[tid] = eb[tid];
    __syncthreads();
    for (int i = 0; i < NLAY; ++i) {
        for (int t = tid; t < 2560; t += 256) g_A[i * 2560 + t] = Ash[t];
        g_d[i * 256 + tid] = dsh[tid];
        __syncthreads();
        if (i == NLAY - 1) break;
        const float* Wp = Weu + (size_t)i * 65536;
        float accA[10];
        #pragma unroll
        for (int k = 0; k < 10; ++k) accA[k] = 0.f;
        float accd = 0.f;
        for (int c = 0; c < 256; ++c) {
            float w = Wp[c * 256 + tid];
            accd = fmaf(dsh[c], w, accd);
            #pragma unroll
            for (int k = 0; k < 10; ++k) accA[k] = fmaf(Ash[k * 256 + c], w, accA[k]);
        }
        accd += beu[i * 256 + tid];
        __syncthreads();
        #pragma unroll
        for (int k = 0; k < 10; ++k) Ash[k * 256 + tid] = accA[k];
        dsh[tid] = accd;
        __syncthreads();
    }
}
__global__ void bmat_kernel(const float* __restrict__ We) {
    __shared__ float Ash[10 * 256];
    __shared__ float dsh[256];
    int i = blockIdx.x, tid = threadIdx.x;
    for (int t = tid; t < 2560; t += 256) Ash[t] = g_A[i * 2560 + t];
    dsh[tid] = g_d[i * 256 + tid];
    __syncthreads();
    const float* Wp = We + (size_t)i * 65536;
    float accB[10];
    #pragma unroll
    for (int k = 0; k < 10; ++k) accB[k] = 0.f;
    float accc = 0.f;
    for (int c = 0; c < 256; ++c) {
        float w = Wp[c * 256 + tid];
        accc = fmaf(dsh[c], w, accc);
        #pragma unroll
        for (int k = 0; k < 10; ++k) accB[k] = fmaf(Ash[k * 256 + c], w, accB[k]);
    }
    #pragma unroll
    for (int k = 0; k < 10; ++k) g_B[i * 2560 + k * 256 + tid] = accB[k];
    g_c[i * 256 + tid] = accc;
}

// ---------------- weight transpose + fp16 split ----------------
__global__ void wprep_kernel(const float* __restrict__ Wl, const float* __restrict__ Wr,
                             const float* __restrict__ oW1) {
    int idx = blockIdx.x * 256 + threadIdx.x;
    const int LTOT = NLAY * 512 * 256;
    float v;
    if (idx < LTOT) {
        int l = idx >> 17;
        int rem = idx & 131071;
        int row = rem >> 8, k = rem & 255;
        v = (row < 256) ? Wl[(size_t)l * 65536 + k * 256 + row]
                        : Wr[(size_t)l * 65536 + k * 256 + (row - 256)];
    } else if (idx < LTOT + 128 * 256) {
        int rem = idx - LTOT;
        int row = rem >> 8, k = rem & 255;
        v = oW1[k * 128 + row];
    } else return;
    __half hi, lo;
    split_f16(v, hi, lo);
    g_WTh[idx] = hi; g_WTl[idx] = lo;
}

// ---------------- node encoder ----------------
__global__ void encoder_kernel(const float* __restrict__ x, const float* __restrict__ nW,
                               const float* __restrict__ nb) {
    int idx = blockIdx.x * 256 + threadIdx.x;
    int n = idx >> 8, c = idx & 255;
    if (n >= NN) return;
    float s = nb[c];
    #pragma unroll
    for (int k = 0; k < 13; ++k) s = fmaf(x[n * 13 + k], nW[k * 256 + c], s);
    __half hi, lo;
    split_f16(s, hi, lo);
    g_hh[0][idx] = hi; g_hl[0][idx] = lo;
}

// ---------------- 3xFP16 mma.sync GEMM, cp.async double-buffered ----------------
#define SA 40
#define ARR_H 5120
#define BUF_H (4 * ARR_H)
#define GSMEM_BYTES (2 * BUF_H * 2)

__global__ __launch_bounds__(256, 2)
void mma_gemm(int hsel, int wrow0, const float* __restrict__ bias0,
              const float* __restrict__ bias1, int outmode, float slope) {
    extern __shared__ __align__(16) __half sm[];
    const __half* __restrict__ Ah = g_hh[hsel];
    const __half* __restrict__ Al = g_hl[hsel];

    int tid = threadIdx.x;
    int wid = tid >> 5, lane = tid & 31;
    int warp_m = wid & 1, warp_n = wid >> 1;
    int m0 = blockIdx.x * 128;
    int colg = blockIdx.y * 128;
    int tig = lane & 3, grp = lane >> 2;

    float c[4][4][4];
    #pragma unroll
    for (int mi = 0; mi < 4; ++mi)
        #pragma unroll
        for (int ni = 0; ni < 4; ++ni)
            #pragma unroll
            for (int j = 0; j < 4; ++j) c[mi][ni][j] = 0.f;

    auto issue = [&](int kb, int buf) {
        int kt = kb * 32;
        __half* base = sm + buf * BUF_H;
        #pragma unroll
        for (int i = 0; i < 8; ++i) {
            int slot = tid + i * 256;
            int arr = slot >> 9;
            int rc = slot & 511;
            int r = rc >> 2, ch = rc & 3;
            const __half* src;
            int bytes = 16;
            if (arr < 2) {
                int gm = m0 + r;
                if (gm >= NN) { gm = NN - 1; bytes = 0; }
                src = (arr == 0 ? Ah : Al) + (size_t)gm * 256 + kt + ch * 8;
            } else {
                int row = wrow0 + colg + r;
                src = (arr == 2 ? g_WTh : g_WTl) + (size_t)row * 256 + kt + ch * 8;
            }
            uint32_t dst = smem_u32(base + arr * ARR_H + r * SA + ch * 8);
            cp16(dst, src, bytes);
        }
        cp_commit();
    };

    issue(0, 0);
    for (int kb = 0; kb < 8; ++kb) {
        if (kb < 7) {
            issue(kb + 1, (kb + 1) & 1);
            asm volatile("cp.async.wait_group 1;" ::: "memory");
        } else {
            asm volatile("cp.async.wait_group 0;" ::: "memory");
        }
        __syncthreads();

        const __half* base = sm + (kb & 1) * BUF_H;
        const __half* Abh = base;
        const __half* Abl = base + ARR_H;
        const __half* Bbh = base + 2 * ARR_H;
        const __half* Bbl = base + 3 * ARR_H;

        #pragma unroll
        for (int ks = 0; ks < 2; ++ks) {
            int k0 = ks * 16;
            uint32_t bh[4][2], bl[4][2];
            #pragma unroll
            for (int ni = 0; ni < 4; ++ni) {
                int nb = (warp_n * 32 + ni * 8 + grp) * SA + k0 + tig * 2;
                bh[ni][0] = *(const uint32_t*)&Bbh[nb];
                bh[ni][1] = *(const uint32_t*)&Bbh[nb + 8];
                bl[ni][0] = *(const uint32_t*)&Bbl[nb];
                bl[ni][1] = *(const uint32_t*)&Bbl[nb + 8];
            }
            #pragma unroll
            for (int mi = 0; mi < 4; ++mi) {
                int ab = (warp_m * 64 + mi * 16 + grp) * SA + k0 + tig * 2;
                uint32_t ah[4], al[4];
                ah[0] = *(const uint32_t*)&Abh[ab];
                ah[1] = *(const uint32_t*)&Abh[ab + 8 * SA];
                ah[2] = *(const uint32_t*)&Abh[ab + 8];
                ah[3] = *(const uint32_t*)&Abh[ab + 8 * SA + 8];
                al[0] = *(const uint32_t*)&Abl[ab];
                al[1] = *(const uint32_t*)&Abl[ab + 8 * SA];
                al[2] = *(const uint32_t*)&Abl[ab + 8];
                al[3] = *(const uint32_t*)&Abl[ab + 8 * SA + 8];
                #pragma unroll
                for (int ni = 0; ni < 4; ++ni) {
                    mma_f16(c[mi][ni], ah, bh[ni]);
                    mma_f16(c[mi][ni], ah, bl[ni]);
                    mma_f16(c[mi][ni], al, bh[ni]);
                }
            }
        }
        __syncthreads();
    }

    #pragma unroll
    for (int mi = 0; mi < 4; ++mi) {
        #pragma unroll
        for (int ni = 0; ni < 4; ++ni) {
            int gn = colg + warp_n * 32 + ni * 8 + tig * 2;
            float* outp; const float* bp; int cc, ld;
            if (outmode)        { outp = g_t;  bp = bias0; cc = gn;       ld = 128; }
            else if (gn < 256)  { outp = g_xl; bp = bias0; cc = gn;       ld = 256; }
            else                { outp = g_xr; bp = bias1; cc = gn - 256; ld = 256; }
            float b0v = bp[cc], b1v = bp[cc + 1];
            int gm = m0 + warp_m * 64 + mi * 16 + grp;
            if (gm < NN) {
                float v0 = c[mi][ni][0] + b0v; v0 = v0 >= 0.f ? v0 : slope * v0;
                float v1 = c[mi][ni][1] + b1v; v1 = v1 >= 0.f ? v1 : slope * v1;
                *(float2*)(outp + (size_t)gm * ld + cc) = make_float2(v0, v1);
            }
            int gm2 = gm + 8;
            if (gm2 < NN) {
                float v0 = c[mi][ni][2] + b0v; v0 = v0 >= 0.f ? v0 : slope * v0;
                float v1 = c[mi][ni][3] + b1v; v1 = v1 >= 0.f ? v1 : slope * v1;
                *(float2*)(outp + (size_t)gm2 * ld + cc) = make_float2(v0, v1);
            }
        }
    }
}

// ---------------- phase 1: per-edge logits -> expw ----------------
// one warp per edge (contiguous chunks), lane owns channels [lane*8, lane*8+8).
__global__ __launch_bounds__(128)
void edge_kernel(int layer, const float* __restrict__ att) {
    int lane = threadIdx.x & 31;
    int gw = (blockIdx.x * 128 + threadIdx.x) >> 5;
    int nw = gridDim.x * 4;

    // per-lane constants in registers
    float Brg[10][8], attr[8], cr[8];
    int c0 = lane * 8;
    #pragma unroll
    for (int k = 0; k < 10; ++k) {
        float4 b0 = *(const float4*)(g_B + layer * 2560 + k * 256 + c0);
        float4 b1 = *(const float4*)(g_B + layer * 2560 + k * 256 + c0 + 4);
        Brg[k][0] = b0.x; Brg[k][1] = b0.y; Brg[k][2] = b0.z; Brg[k][3] = b0.w;
        Brg[k][4] = b1.x; Brg[k][5] = b1.y; Brg[k][6] = b1.z; Brg[k][7] = b1.w;
    }
    {
        float4 a0 = *(const float4*)(att + layer * 256 + c0);
        float4 a1 = *(const float4*)(att + layer * 256 + c0 + 4);
        attr[0] = a0.x; attr[1] = a0.y; attr[2] = a0.z; attr[3] = a0.w;
        attr[4] = a1.x; attr[5] = a1.y; attr[6] = a1.z; attr[7] = a1.w;
        float4 d0 = *(const float4*)(g_c + layer * 256 + c0);
        float4 d1 = *(const float4*)(g_c + layer * 256 + c0 + 4);
        cr[0] = d0.x; cr[1] = d0.y; cr[2] = d0.z; cr[3] = d0.w;
        cr[4] = d1.x; cr[5] = d1.y; cr[6] = d1.z; cr[7] = d1.w;
    }

    int chunk = (EE + nw - 1) / nw;
    int p0 = gw * chunk;
    int p1 = min(p0 + chunk, EE);
    for (int p = p0; p < p1; ++p) {
        int sn = g_srcs[p], dn = g_dsts[p];
        const float2* ea2 = (const float2*)(g_eas + (size_t)p * 10);
        float2 a0 = ea2[0], a1 = ea2[1], a2 = ea2[2], a3 = ea2[3], a4 = ea2[4];
        float ea[10] = {a0.x, a0.y, a1.x, a1.y, a2.x, a2.y, a3.x, a3.y, a4.x, a4.y};

        float4 x0 = *(const float4*)(g_xl + (size_t)sn * 256 + c0);
        float4 x1 = *(const float4*)(g_xl + (size_t)sn * 256 + c0 + 4);
        float4 r0 = *(const float4*)(g_xr + (size_t)dn * 256 + c0);
        float4 r1 = *(const float4*)(g_xr + (size_t)dn * 256 + c0 + 4);
        float xl8[8] = {x0.x, x0.y, x0.z, x0.w, x1.x, x1.y, x1.z, x1.w};
        float xr8[8] = {r0.x, r0.y, r0.z, r0.w, r1.x, r1.y, r1.z, r1.w};

        float m[8];
        #pragma unroll
        for (int j = 0; j < 8; ++j) m[j] = cr[j];
        #pragma unroll
        for (int k = 0; k < 10; ++k)
            #pragma unroll
            for (int j = 0; j < 8; ++j) m[j] = fmaf(ea[k], Brg[k][j], m[j]);
        float s = 0.f;
        #pragma unroll
        for (int j = 0; j < 8; ++j) {
            float v = m[j] + xl8[j] + xr8[j];
            v = v >= 0.f ? v : 0.2f * v;          // leaky 0.2
            s = fmaf(v, attr[j], s);
        }
        // reduce within quad -> logit for head lane>>2
        s += __shfl_xor_sync(0xffffffffu, s, 1);
        s += __shfl_xor_sync(0xffffffffu, s, 2);
        float w = __expf(s);
        if ((lane & 3) == 0) g_expw[(size_t)p * 8 + (lane >> 2)] = w;
    }
}

// ---------------- phase 2: per-node softmax-normalize + aggregate + BN ----------------
__global__ __launch_bounds__(256)
void node_kernel(int layer, int hin,
                 const float* __restrict__ conv_b,
                 const float* __restrict__ bng, const float* __restrict__ bnb,
                 const float* __restrict__ bnrm, const float* __restrict__ bnrv) {
    int tid = threadIdx.x;
    int warp = tid >> 5, lane = tid & 31;
    int n = blockIdx.x * 8 + warp;
    if (n >= NN) return;
    int hout = hin ^ 1;
    int s0 = g_start[n], s1 = g_start[n + 1];

    // pass A: den per head (coalesced 128B chunks; position i keeps h = lane&7)
    float den = 0.f;
    for (int i = s0 * 8 + lane; i < s1 * 8; i += 32) den += g_expw[i];
    den += __shfl_xor_sync(0xffffffffu, den, 8);
    den += __shfl_xor_sync(0xffffffffu, den, 16);
    float invden = 1.f / (den + 1e-16f);   // lanes 0-7 hold head lane's invden

    // pass B: aggregate
    float acc[8];
    #pragma unroll
    for (int h = 0; h < 8; ++h) acc[h] = 0.f;
    for (int p = s0; p < s1; ++p) {
        int sn = g_srcs[p];
        float w = 0.f;
        if (lane < 8) w = g_expw[(size_t)p * 8 + lane] * invden;
        float val[8];
        #pragma unroll
        for (int h = 0; h < 8; ++h) val[h] = __shfl_sync(0xffffffffu, w, h);
        #pragma unroll
        for (int h = 0; h < 8; ++h) {
            float xls = g_xl[(size_t)sn * 256 + h * 32 + lane];
            acc[h] = fmaf(val[h], xls, acc[h]);
        }
    }

    // epilogue: conv bias + BN + leaky + residual + fp16 split
    #pragma unroll
    for (int h = 0; h < 8; ++h) {
        int ch = h * 32 + lane;
        size_t idx = (size_t)n * 256 + ch;
        float sc = bng[layer * 256 + ch] * rsqrtf(bnrv[layer * 256 + ch] + 1e-5f);
        float sh = bnb[layer * 256 + ch] - bnrm[layer * 256 + ch] * sc;
        float v = acc[h] + conv_b[layer * 256 + ch];
        v = v * sc + sh;
        v = v >= 0.f ? v : 0.01f * v;
        if (layer >= 1)
            v += __half2float(g_hh[hin][idx]) + __half2float(g_hl[hin][idx]);
        __half hi, lo;
        split_f16(v, hi, lo);
        g_hh[hout][idx] = hi;
        g_hl[hout][idx] = lo;
    }
}

// ---------------- head: out = t @ W2 + b2 ----------------
__global__ void head2_kernel(const float* __restrict__ W2, const float* __restrict__ b2,
                             float* __restrict__ out) {
    __shared__ float w[128];
    int tid = threadIdx.x;
    if (tid < 128) w[tid] = W2[tid];
    __syncthreads();
    int n = blockIdx.x * 256 + tid;
    if (n >= NN) return;
    float s = b2[0];
    const float* tp = g_t + (size_t)n * 128;
    #pragma unroll
    for (int j = 0; j < 128; ++j) s = fmaf(tp[j], w[j], s);
    out[n] = s;
}

// ---------------- launch ----------------
extern "C" void kernel_launch(void* const* d_in, const int* in_sizes, int n_in,
                              void* d_out, int out_size) {
    const float* x      = (const float*)d_in[0];
    const int*   ei     = (const int*)d_in[1];
    const float* eattr  = (const float*)d_in[2];
    const float* nW     = (const float*)d_in[3];
    const float* nb     = (const float*)d_in[4];
    const float* eW     = (const float*)d_in[5];
    const float* eb     = (const float*)d_in[6];
    const float* Wl     = (const float*)d_in[7];
    const float* bl     = (const float*)d_in[8];
    const float* Wr     = (const float*)d_in[9];
    const float* br     = (const float*)d_in[10];
    const float* We     = (const float*)d_in[11];
    const float* att    = (const float*)d_in[12];
    const float* conv_b = (const float*)d_in[13];
    const float* Weu    = (const float*)d_in[14];
    const float* beu    = (const float*)d_in[15];
    const float* bng    = (const float*)d_in[16];
    const float* bnb    = (const float*)d_in[17];
    const float* bnrm   = (const float*)d_in[18];
    const float* bnrv   = (const float*)d_in[19];
    const float* oW1    = (const float*)d_in[20];
    const float* ob1    = (const float*)d_in[21];
    const float* oW2    = (const float*)d_in[22];
    const float* ob2    = (const float*)d_in[23];

    const int* srcp = ei;
    const int* dstp = ei + EE;

    static int attr_set = 0;
    if (!attr_set) {
        cudaFuncSetAttribute(mma_gemm, cudaFuncAttributeMaxDynamicSharedMemorySize,
                             GSMEM_BYTES);
        attr_set = 1;
    }

    // CSR build (deterministic) + sorted edge arrays
    zero_kernel<<<(NN + 256) / 256, 256>>>();
    count_kernel<<<(EE + 255) / 256, 256>>>(dstp);
    scan_kernel<<<1, 1024>>>();
    fill_kernel<<<(EE + 255) / 256, 256>>>(dstp);
    sort_kernel<<<(NN + 127) / 128, 128>>>();
    gather_kernel<<<(EE + 255) / 256, 256>>>(srcp, dstp, eattr);

    // edge matrix chain + weight prep
    chain_kernel<<<1, 256>>>(eW, eb, Weu, beu);
    bmat_kernel<<<NLAY, 256>>>(We);
    wprep_kernel<<<3200, 256>>>(Wl, Wr, oW1);

    // node encoder
    encoder_kernel<<<NN, 256>>>(x, nW, nb);

    const int MT = (NN + 127) / 128;   // 235
    dim3 gemm_grid(MT, 4);
    dim3 head_grid(MT, 1);
    int cur = 0;
    for (int i = 0; i < NLAY; ++i) {
        mma_gemm<<<gemm_grid, 256, GSMEM_BYTES>>>(cur, i * 512, bl + i * 256, br + i * 256,
                                                  /*outmode=*/0, /*slope=*/1.0f);
        edge_kernel<<<2048, 128>>>(i, att);
        node_kernel<<<(NN + 7) / 8, 256>>>(i, cur, conv_b, bng, bnb, bnrm, bnrv);
        cur ^= 1;
    }

    // output head
    mma_gemm<<<head_grid, 256, GSMEM_BYTES>>>(cur, NLAY * 512, ob1, (const float*)0,
                                              /*outmode=*/1, /*slope=*/0.01f);
    head2_kernel<<<(NN + 255) / 256, 256>>>(oW2, ob2, (float*)d_out);
}

// round 6
// speedup vs baseline: 1.9523x; 1.1081x over previous
#include <cuda_runtime.h>
#include <cuda_fp16.h>
#include <math.h>
#include <stdint.h>

#define NN    30000
#define EE    480000
#define HIDN  256
#define NLAY  6

// ---------------- static device scratch ----------------
static __device__ __align__(128) __half g_hh[2][NN * HIDN];   // h split hi (fp16)
static __device__ __align__(128) __half g_hl[2][NN * HIDN];   // h split lo (fp16)
static __device__ __align__(128) float  g_xl[NN * HIDN];
static __device__ __align__(128) float  g_xr[NN * HIDN];
static __device__ __align__(128) float  g_t[NN * 128];
static __device__ __align__(128) __half g_WTh[(NLAY * 512 + 128) * 256];
static __device__ __align__(128) __half g_WTl[(NLAY * 512 + 128) * 256];
static __device__ __align__(128) float  g_B[NLAY * 10 * 256];
static __device__ __align__(128) float  g_c[NLAY * 256];
static __device__ __align__(128) float  g_A[NLAY * 10 * 256];
static __device__ __align__(128) float  g_d[NLAY * 256];
static __device__ int g_cnt[NN + 1];
static __device__ int g_start[NN + 1];
static __device__ int g_cursor[NN + 1];
static __device__ int g_eid[EE];
// dst-sorted edge data (built once)
static __device__ __align__(128) int   g_srcs[EE];
static __device__ __align__(128) float g_eas[EE * 10];

// ---------------- helpers ----------------
__device__ __forceinline__ void split_f16(float x, __half& hi, __half& lo) {
    hi = __float2half_rn(x);
    lo = __float2half_rn(x - __half2float(hi));
}

__device__ __forceinline__ uint32_t smem_u32(const void* p) {
    uint32_t a;
    asm("{ .reg .u64 t; cvta.to.shared.u64 t, %1; cvt.u32.u64 %0, t; }" : "=r"(a) : "l"(p));
    return a;
}

__device__ __forceinline__ void cp16(uint32_t dst, const void* src, int bytes) {
    asm volatile("cp.async.cg.shared.global [%0], [%1], 16, %2;"
                 :: "r"(dst), "l"(src), "r"(bytes));
}
__device__ __forceinline__ void cp_commit() {
    asm volatile("cp.async.commit_group;" ::: "memory");
}

__device__ __forceinline__ void mma_f16(float* d, const uint32_t* a, const uint32_t* b) {
    asm volatile(
        "mma.sync.aligned.m16n8k16.row.col.f32.f16.f16.f32 "
        "{%0,%1,%2,%3}, {%4,%5,%6,%7}, {%8,%9}, {%0,%1,%2,%3};"
        : "+f"(d[0]), "+f"(d[1]), "+f"(d[2]), "+f"(d[3])
        : "r"(a[0]), "r"(a[1]), "r"(a[2]), "r"(a[3]), "r"(b[0]), "r"(b[1]));
}

// ---------------- CSR build ----------------
__global__ void zero_kernel() {
    int i = blockIdx.x * 256 + threadIdx.x;
    if (i <= NN) g_cnt[i] = 0;
}
__global__ void count_kernel(const int* __restrict__ dst) {
    int e = blockIdx.x * 256 + threadIdx.x;
    if (e < EE) atomicAdd(&g_cnt[dst[e]], 1);
}
__global__ void scan_kernel() {
    __shared__ int part[1024];
    const int T = 1024, ITEMS = (NN + T - 1) / T;
    int tid = threadIdx.x, base = tid * ITEMS, s = 0;
    for (int i = 0; i < ITEMS; ++i) { int idx = base + i; if (idx < NN) s += g_cnt[idx]; }
    part[tid] = s;
    __syncthreads();
    for (int off = 1; off < T; off <<= 1) {
        int v = 0;
        if (tid >= off) v = part[tid - off];
        __syncthreads();
        part[tid] += v;
        __syncthreads();
    }
    int run = (tid == 0) ? 0 : part[tid - 1];
    for (int i = 0; i < ITEMS; ++i) {
        int idx = base + i;
        if (idx < NN) { g_start[idx] = run; g_cursor[idx] = run; run += g_cnt[idx]; }
    }
    if (tid == T - 1) g_start[NN] = part[T - 1];
}
__global__ void fill_kernel(const int* __restrict__ dst) {
    int e = blockIdx.x * 256 + threadIdx.x;
    if (e < EE) { int pos = atomicAdd(&g_cursor[dst[e]], 1); g_eid[pos] = e; }
}
// deterministic order: sort each node's list in a local buffer
__global__ void sort_kernel() {
    int n = blockIdx.x * 128 + threadIdx.x;
    if (n >= NN) return;
    int s0 = g_start[n], s1 = g_start[n + 1];
    int d = s1 - s0;
    if (d <= 1) return;
    if (d <= 96) {
        int buf[96];
        for (int i = 0; i < d; ++i) buf[i] = g_eid[s0 + i];
        for (int i = 1; i < d; ++i) {
            int v = buf[i], j = i - 1;
            while (j >= 0 && buf[j] > v) { buf[j + 1] = buf[j]; --j; }
            buf[j + 1] = v;
        }
        for (int i = 0; i < d; ++i) g_eid[s0 + i] = buf[i];
    } else {
        for (int i = s0 + 1; i < s1; ++i) {
            int v = g_eid[i], j = i - 1;
            while (j >= s0 && g_eid[j] > v) { g_eid[j + 1] = g_eid[j]; --j; }
            g_eid[j + 1] = v;
        }
    }
}
// materialize dst-sorted edge arrays (once)
__global__ void gather_kernel(const int* __restrict__ src,
                              const float* __restrict__ eattr) {
    int p = blockIdx.x * 256 + threadIdx.x;
    if (p >= EE) return;
    int e = g_eid[p];
    g_srcs[p] = src[e];
    const float* s = eattr + (size_t)e * 10;
    float* d = g_eas + (size_t)p * 10;
    #pragma unroll
    for (int j = 0; j < 10; ++j) d[j] = s[j];
}

// ---------------- edge-matrix chain precompute ----------------
__global__ void chain_kernel(const float* __restrict__ eW, const float* __restrict__ eb,
                             const float* __restrict__ Weu, const float* __restrict__ beu) {
    __shared__ float Ash[10 * 256];
    __shared__ float dsh[256];
    int tid = threadIdx.x;
    for (int t = tid; t < 2560; t += 256) Ash[t] = eW[t];
    dsh[tid] = eb[tid];
    __syncthreads();
    for (int i = 0; i < NLAY; ++i) {
        for (int t = tid; t < 2560; t += 256) g_A[i * 2560 + t] = Ash[t];
        g_d[i * 256 + tid] = dsh[tid];
        __syncthreads();
        if (i == NLAY - 1) break;
        const float* Wp = Weu + (size_t)i * 65536;
        float accA[10];
        #pragma unroll
        for (int k = 0; k < 10; ++k) accA[k] = 0.f;
        float accd = 0.f;
        for (int c = 0; c < 256; ++c) {
            float w = Wp[c * 256 + tid];
            accd = fmaf(dsh[c], w, accd);
            #pragma unroll
            for (int k = 0; k < 10; ++k) accA[k] = fmaf(Ash[k * 256 + c], w, accA[k]);
        }
        accd += beu[i * 256 + tid];
        __syncthreads();
        #pragma unroll
        for (int k = 0; k < 10; ++k) Ash[k * 256 + tid] = accA[k];
        dsh[tid] = accd;
        __syncthreads();
    }
}
__global__ void bmat_kernel(const float* __restrict__ We) {
    __shared__ float Ash[10 * 256];
    __shared__ float dsh[256];
    int i = blockIdx.x, tid = threadIdx.x;
    for (int t = tid; t < 2560; t += 256) Ash[t] = g_A[i * 2560 + t];
    dsh[tid] = g_d[i * 256 + tid];
    __syncthreads();
    const float* Wp = We + (size_t)i * 65536;
    float accB[10];
    #pragma unroll
    for (int k = 0; k < 10; ++k) accB[k] = 0.f;
    float accc = 0.f;
    for (int c = 0; c < 256; ++c) {
        float w = Wp[c * 256 + tid];
        accc = fmaf(dsh[c], w, accc);
        #pragma unroll
        for (int k = 0; k < 10; ++k) accB[k] = fmaf(Ash[k * 256 + c], w, accB[k]);
    }
    #pragma unroll
    for (int k = 0; k < 10; ++k) g_B[i * 2560 + k * 256 + tid] = accB[k];
    g_c[i * 256 + tid] = accc;
}

// ---------------- weight transpose + fp16 split ----------------
__global__ void wprep_kernel(const float* __restrict__ Wl, const float* __restrict__ Wr,
                             const float* __restrict__ oW1) {
    int idx = blockIdx.x * 256 + threadIdx.x;
    const int LTOT = NLAY * 512 * 256;
    float v;
    if (idx < LTOT) {
        int l = idx >> 17;
        int rem = idx & 131071;
        int row = rem >> 8, k = rem & 255;
        v = (row < 256) ? Wl[(size_t)l * 65536 + k * 256 + row]
                        : Wr[(size_t)l * 65536 + k * 256 + (row - 256)];
    } else if (idx < LTOT + 128 * 256) {
        int rem = idx - LTOT;
        int row = rem >> 8, k = rem & 255;
        v = oW1[k * 128 + row];
    } else return;
    __half hi, lo;
    split_f16(v, hi, lo);
    g_WTh[idx] = hi; g_WTl[idx] = lo;
}

// ---------------- node encoder ----------------
__global__ void encoder_kernel(const float* __restrict__ x, const float* __restrict__ nW,
                               const float* __restrict__ nb) {
    int idx = blockIdx.x * 256 + threadIdx.x;
    int n = idx >> 8, c = idx & 255;
    if (n >= NN) return;
    float s = nb[c];
    #pragma unroll
    for (int k = 0; k < 13; ++k) s = fmaf(x[n * 13 + k], nW[k * 256 + c], s);
    __half hi, lo;
    split_f16(s, hi, lo);
    g_hh[0][idx] = hi; g_hl[0][idx] = lo;
}

// ---------------- 3xFP16 mma.sync GEMM, cp.async double-buffered ----------------
#define SA 40
#define ARR_H 5120
#define BUF_H (4 * ARR_H)
#define GSMEM_BYTES (2 * BUF_H * 2)

__global__ __launch_bounds__(256, 2)
void mma_gemm(int hsel, int wrow0, const float* __restrict__ bias0,
              const float* __restrict__ bias1, int outmode, float slope) {
    extern __shared__ __align__(16) __half sm[];
    const __half* __restrict__ Ah = g_hh[hsel];
    const __half* __restrict__ Al = g_hl[hsel];

    int tid = threadIdx.x;
    int wid = tid >> 5, lane = tid & 31;
    int warp_m = wid & 1, warp_n = wid >> 1;
    int m0 = blockIdx.x * 128;
    int colg = blockIdx.y * 128;
    int tig = lane & 3, grp = lane >> 2;

    float c[4][4][4];
    #pragma unroll
    for (int mi = 0; mi < 4; ++mi)
        #pragma unroll
        for (int ni = 0; ni < 4; ++ni)
            #pragma unroll
            for (int j = 0; j < 4; ++j) c[mi][ni][j] = 0.f;

    auto issue = [&](int kb, int buf) {
        int kt = kb * 32;
        __half* base = sm + buf * BUF_H;
        #pragma unroll
        for (int i = 0; i < 8; ++i) {
            int slot = tid + i * 256;
            int arr = slot >> 9;
            int rc = slot & 511;
            int r = rc >> 2, ch = rc & 3;
            const __half* src;
            int bytes = 16;
            if (arr < 2) {
                int gm = m0 + r;
                if (gm >= NN) { gm = NN - 1; bytes = 0; }
                src = (arr == 0 ? Ah : Al) + (size_t)gm * 256 + kt + ch * 8;
            } else {
                int row = wrow0 + colg + r;
                src = (arr == 2 ? g_WTh : g_WTl) + (size_t)row * 256 + kt + ch * 8;
            }
            uint32_t dst = smem_u32(base + arr * ARR_H + r * SA + ch * 8);
            cp16(dst, src, bytes);
        }
        cp_commit();
    };

    issue(0, 0);
    for (int kb = 0; kb < 8; ++kb) {
        if (kb < 7) {
            issue(kb + 1, (kb + 1) & 1);
            asm volatile("cp.async.wait_group 1;" ::: "memory");
        } else {
            asm volatile("cp.async.wait_group 0;" ::: "memory");
        }
        __syncthreads();

        const __half* base = sm + (kb & 1) * BUF_H;
        const __half* Abh = base;
        const __half* Abl = base + ARR_H;
        const __half* Bbh = base + 2 * ARR_H;
        const __half* Bbl = base + 3 * ARR_H;

        #pragma unroll
        for (int ks = 0; ks < 2; ++ks) {
            int k0 = ks * 16;
            uint32_t bh[4][2], bl[4][2];
            #pragma unroll
            for (int ni = 0; ni < 4; ++ni) {
                int nb = (warp_n * 32 + ni * 8 + grp) * SA + k0 + tig * 2;
                bh[ni][0] = *(const uint32_t*)&Bbh[nb];
                bh[ni][1] = *(const uint32_t*)&Bbh[nb + 8];
                bl[ni][0] = *(const uint32_t*)&Bbl[nb];
                bl[ni][1] = *(const uint32_t*)&Bbl[nb + 8];
            }
            #pragma unroll
            for (int mi = 0; mi < 4; ++mi) {
                int ab = (warp_m * 64 + mi * 16 + grp) * SA + k0 + tig * 2;
                uint32_t ah[4], al[4];
                ah[0] = *(const uint32_t*)&Abh[ab];
                ah[1] = *(const uint32_t*)&Abh[ab + 8 * SA];
                ah[2] = *(const uint32_t*)&Abh[ab + 8];
                ah[3] = *(const uint32_t*)&Abh[ab + 8 * SA + 8];
                al[0] = *(const uint32_t*)&Abl[ab];
                al[1] = *(const uint32_t*)&Abl[ab + 8 * SA];
                al[2] = *(const uint32_t*)&Abl[ab + 8];
                al[3] = *(const uint32_t*)&Abl[ab + 8 * SA + 8];
                #pragma unroll
                for (int ni = 0; ni < 4; ++ni) {
                    mma_f16(c[mi][ni], ah, bh[ni]);
                    mma_f16(c[mi][ni], ah, bl[ni]);
                    mma_f16(c[mi][ni], al, bh[ni]);
                }
            }
        }
        __syncthreads();
    }

    #pragma unroll
    for (int mi = 0; mi < 4; ++mi) {
        #pragma unroll
        for (int ni = 0; ni < 4; ++ni) {
            int gn = colg + warp_n * 32 + ni * 8 + tig * 2;
            float* outp; const float* bp; int cc, ld;
            if (outmode)        { outp = g_t;  bp = bias0; cc = gn;       ld = 128; }
            else if (gn < 256)  { outp = g_xl; bp = bias0; cc = gn;       ld = 256; }
            else                { outp = g_xr; bp = bias1; cc = gn - 256; ld = 256; }
            float b0v = bp[cc], b1v = bp[cc + 1];
            int gm = m0 + warp_m * 64 + mi * 16 + grp;
            if (gm < NN) {
                float v0 = c[mi][ni][0] + b0v; v0 = v0 >= 0.f ? v0 : slope * v0;
                float v1 = c[mi][ni][1] + b1v; v1 = v1 >= 0.f ? v1 : slope * v1;
                *(float2*)(outp + (size_t)gm * ld + cc) = make_float2(v0, v1);
            }
            int gm2 = gm + 8;
            if (gm2 < NN) {
                float v0 = c[mi][ni][2] + b0v; v0 = v0 >= 0.f ? v0 : slope * v0;
                float v1 = c[mi][ni][3] + b1v; v1 = v1 >= 0.f ? v1 : slope * v1;
                *(float2*)(outp + (size_t)gm2 * ld + cc) = make_float2(v0, v1);
            }
        }
    }
}

// ---------------- fused attention: one warp per node, xl touched once ----------------
// lane owns channels [lane*8, lane*8+8) -> all in head lane>>2.
// exp-no-max softmax: den += w, accv += w*xl (validated in R5, rel_err 2.8e-6).
__global__ __launch_bounds__(128)
void attn_fused(int layer, int hin,
                const float* __restrict__ att, const float* __restrict__ conv_b,
                const float* __restrict__ bng, const float* __restrict__ bnb,
                const float* __restrict__ bnrm, const float* __restrict__ bnrv) {
    int tid = threadIdx.x;
    int warp = tid >> 5, lane = tid & 31;
    int n = blockIdx.x * 4 + warp;
    if (n >= NN) return;
    int hout = hin ^ 1;
    int c0 = lane * 8;

    // per-lane constants in registers
    float Brg[10][8];
    #pragma unroll
    for (int k = 0; k < 10; ++k) {
        float4 b0 = *(const float4*)(g_B + layer * 2560 + k * 256 + c0);
        float4 b1 = *(const float4*)(g_B + layer * 2560 + k * 256 + c0 + 4);
        Brg[k][0] = b0.x; Brg[k][1] = b0.y; Brg[k][2] = b0.z; Brg[k][3] = b0.w;
        Brg[k][4] = b1.x; Brg[k][5] = b1.y; Brg[k][6] = b1.z; Brg[k][7] = b1.w;
    }
    float attr[8], cr[8], xr8[8];
    {
        float4 a0 = *(const float4*)(att + layer * 256 + c0);
        float4 a1 = *(const float4*)(att + layer * 256 + c0 + 4);
        attr[0] = a0.x; attr[1] = a0.y; attr[2] = a0.z; attr[3] = a0.w;
        attr[4] = a1.x; attr[5] = a1.y; attr[6] = a1.z; attr[7] = a1.w;
        float4 d0 = *(const float4*)(g_c + layer * 256 + c0);
        float4 d1 = *(const float4*)(g_c + layer * 256 + c0 + 4);
        cr[0] = d0.x; cr[1] = d0.y; cr[2] = d0.z; cr[3] = d0.w;
        cr[4] = d1.x; cr[5] = d1.y; cr[6] = d1.z; cr[7] = d1.w;
        float4 r0 = *(const float4*)(g_xr + (size_t)n * 256 + c0);
        float4 r1 = *(const float4*)(g_xr + (size_t)n * 256 + c0 + 4);
        xr8[0] = r0.x; xr8[1] = r0.y; xr8[2] = r0.z; xr8[3] = r0.w;
        xr8[4] = r1.x; xr8[5] = r1.y; xr8[6] = r1.z; xr8[7] = r1.w;
    }

    float accv[8];
    #pragma unroll
    for (int j = 0; j < 8; ++j) accv[j] = 0.f;
    float den = 0.f;

    int s0 = g_start[n], s1 = g_start[n + 1];
    for (int p = s0; p < s1; ++p) {
        int sn = g_srcs[p];
        const float2* ea2 = (const float2*)(g_eas + (size_t)p * 10);
        float2 a0 = ea2[0], a1 = ea2[1], a2 = ea2[2], a3 = ea2[3], a4 = ea2[4];
        float ea[10] = {a0.x, a0.y, a1.x, a1.y, a2.x, a2.y, a3.x, a3.y, a4.x, a4.y};

        float4 x0 = *(const float4*)(g_xl + (size_t)sn * 256 + c0);
        float4 x1 = *(const float4*)(g_xl + (size_t)sn * 256 + c0 + 4);
        float xl8[8] = {x0.x, x0.y, x0.z, x0.w, x1.x, x1.y, x1.z, x1.w};

        float m[8];
        #pragma unroll
        for (int j = 0; j < 8; ++j) m[j] = cr[j];
        #pragma unroll
        for (int k = 0; k < 10; ++k)
            #pragma unroll
            for (int j = 0; j < 8; ++j) m[j] = fmaf(ea[k], Brg[k][j], m[j]);

        float s = 0.f;
        #pragma unroll
        for (int j = 0; j < 8; ++j) {
            float v = m[j] + xl8[j] + xr8[j];
            v = v >= 0.f ? v : 0.2f * v;          // leaky 0.2
            s = fmaf(v, attr[j], s);
        }
        // quad reduce -> this lane's head logit
        s += __shfl_xor_sync(0xffffffffu, s, 1);
        s += __shfl_xor_sync(0xffffffffu, s, 2);
        float w = __expf(s);
        den += w;
        #pragma unroll
        for (int j = 0; j < 8; ++j) accv[j] = fmaf(w, xl8[j], accv[j]);
    }

    float invden = 1.f / (den + 1e-16f);

    // epilogue: conv bias + BN + leaky + residual + fp16 split (16B vectorized)
    float4 cb0 = *(const float4*)(conv_b + layer * 256 + c0);
    float4 cb1 = *(const float4*)(conv_b + layer * 256 + c0 + 4);
    float4 g0  = *(const float4*)(bng + layer * 256 + c0);
    float4 g1  = *(const float4*)(bng + layer * 256 + c0 + 4);
    float4 bb0 = *(const float4*)(bnb + layer * 256 + c0);
    float4 bb1 = *(const float4*)(bnb + layer * 256 + c0 + 4);
    float4 rm0 = *(const float4*)(bnrm + layer * 256 + c0);
    float4 rm1 = *(const float4*)(bnrm + layer * 256 + c0 + 4);
    float4 rv0 = *(const float4*)(bnrv + layer * 256 + c0);
    float4 rv1 = *(const float4*)(bnrv + layer * 256 + c0 + 4);
    float cb[8] = {cb0.x, cb0.y, cb0.z, cb0.w, cb1.x, cb1.y, cb1.z, cb1.w};
    float gg[8] = {g0.x, g0.y, g0.z, g0.w, g1.x, g1.y, g1.z, g1.w};
    float bbv[8] = {bb0.x, bb0.y, bb0.z, bb0.w, bb1.x, bb1.y, bb1.z, bb1.w};
    float rm[8] = {rm0.x, rm0.y, rm0.z, rm0.w, rm1.x, rm1.y, rm1.z, rm1.w};
    float rv[8] = {rv0.x, rv0.y, rv0.z, rv0.w, rv1.x, rv1.y, rv1.z, rv1.w};

    size_t base = (size_t)n * 256 + c0;
    __half resh[8], resl[8];
    if (layer >= 1) {
        *(uint4*)resh = *(const uint4*)(&g_hh[hin][base]);
        *(uint4*)resl = *(const uint4*)(&g_hl[hin][base]);
    }
    __half oh[8], ol[8];
    #pragma unroll
    for (int j = 0; j < 8; ++j) {
        float sc = gg[j] * rsqrtf(rv[j] + 1e-5f);
        float sh = bbv[j] - rm[j] * sc;
        float v = accv[j] * invden + cb[j];
        v = v * sc + sh;
        v = v >= 0.f ? v : 0.01f * v;
        if (layer >= 1) v += __half2float(resh[j]) + __half2float(resl[j]);
        split_f16(v, oh[j], ol[j]);
    }
    *(uint4*)(&g_hh[hout][base]) = *(const uint4*)oh;
    *(uint4*)(&g_hl[hout][base]) = *(const uint4*)ol;
}

// ---------------- head: out = t @ W2 + b2 ----------------
__global__ void head2_kernel(const float* __restrict__ W2, const float* __restrict__ b2,
                             float* __restrict__ out) {
    __shared__ float w[128];
    int tid = threadIdx.x;
    if (tid < 128) w[tid] = W2[tid];
    __syncthreads();
    int n = blockIdx.x * 256 + tid;
    if (n >= NN) return;
    float s = b2[0];
    const float* tp = g_t + (size_t)n * 128;
    #pragma unroll
    for (int j = 0; j < 128; ++j) s = fmaf(tp[j], w[j], s);
    out[n] = s;
}

// ---------------- launch ----------------
extern "C" void kernel_launch(void* const* d_in, const int* in_sizes, int n_in,
                              void* d_out, int out_size) {
    const float* x      = (const float*)d_in[0];
    const int*   ei     = (const int*)d_in[1];
    const float* eattr  = (const float*)d_in[2];
    const float* nW     = (const float*)d_in[3];
    const float* nb     = (const float*)d_in[4];
    const float* eW     = (const float*)d_in[5];
    const float* eb     = (const float*)d_in[6];
    const float* Wl     = (const float*)d_in[7];
    const float* bl     = (const float*)d_in[8];
    const float* Wr     = (const float*)d_in[9];
    const float* br     = (const float*)d_in[10];
    const float* We     = (const float*)d_in[11];
    const float* att    = (const float*)d_in[12];
    const float* conv_b = (const float*)d_in[13];
    const float* Weu    = (const float*)d_in[14];
    const float* beu    = (const float*)d_in[15];
    const float* bng    = (const float*)d_in[16];
    const float* bnb    = (const float*)d_in[17];
    const float* bnrm   = (const float*)d_in[18];
    const float* bnrv   = (const float*)d_in[19];
    const float* oW1    = (const float*)d_in[20];
    const float* ob1    = (const float*)d_in[21];
    const float* oW2    = (const float*)d_in[22];
    const float* ob2    = (const float*)d_in[23];

    const int* srcp = ei;
    const int* dstp = ei + EE;

    static int attr_set = 0;
    if (!attr_set) {
        cudaFuncSetAttribute(mma_gemm, cudaFuncAttributeMaxDynamicSharedMemorySize,
                             GSMEM_BYTES);
        attr_set = 1;
    }

    // CSR build (deterministic) + sorted edge arrays
    zero_kernel<<<(NN + 256) / 256, 256>>>();
    count_kernel<<<(EE + 255) / 256, 256>>>(dstp);
    scan_kernel<<<1, 1024>>>();
    fill_kernel<<<(EE + 255) / 256, 256>>>(dstp);
    sort_kernel<<<(NN + 127) / 128, 128>>>();
    gather_kernel<<<(EE + 255) / 256, 256>>>(srcp, eattr);

    // edge matrix chain + weight prep
    chain_kernel<<<1, 256>>>(eW, eb, Weu, beu);
    bmat_kernel<<<NLAY, 256>>>(We);
    wprep_kernel<<<3200, 256>>>(Wl, Wr, oW1);

    // node encoder
    encoder_kernel<<<NN, 256>>>(x, nW, nb);

    const int MT = (NN + 127) / 128;   // 235
    dim3 gemm_grid(MT, 4);
    dim3 head_grid(MT, 1);
    int cur = 0;
    for (int i = 0; i < NLAY; ++i) {
        mma_gemm<<<gemm_grid, 256, GSMEM_BYTES>>>(cur, i * 512, bl + i * 256, br + i * 256,
                                                  /*outmode=*/0, /*slope=*/1.0f);
        attn_fused<<<(NN + 3) / 4, 128>>>(i, cur, att, conv_b, bng, bnb, bnrm, bnrv);
        cur ^= 1;
    }

    // output head
    mma_gemm<<<head_grid, 256, GSMEM_BYTES>>>(cur, NLAY * 512, ob1, (const float*)0,
                                              /*outmode=*/1, /*slope=*/0.01f);
    head2_kernel<<<(NN + 255) / 256, 256>>>(oW2, ob2, (float*)d_out);
}

// round 7
// speedup vs baseline: 2.0373x; 1.0435x over previous
#include <cuda_runtime.h>
#include <cuda_fp16.h>
#include <math.h>
#include <stdint.h>

#define NN    30000
#define EE    480000
#define HIDN  256
#define NLAY  6

// ---------------- static device scratch ----------------
static __device__ __align__(128) __half g_hh[2][NN * HIDN];   // h split hi (fp16)
static __device__ __align__(128) __half g_hl[2][NN * HIDN];   // h split lo (fp16)
static __device__ __align__(128) float  g_xl[NN * HIDN];
static __device__ __align__(128) float  g_xr[NN * HIDN];
static __device__ __align__(128) float  g_t[NN * 128];
static __device__ __align__(128) __half g_WTh[(NLAY * 512 + 128) * 256];
static __device__ __align__(128) __half g_WTl[(NLAY * 512 + 128) * 256];
static __device__ __align__(128) float  g_B[NLAY * 10 * 256];
static __device__ __align__(128) float  g_c[NLAY * 256];
static __device__ __align__(128) float  g_A[NLAY * 10 * 256];
static __device__ __align__(128) float  g_d[NLAY * 256];
static __device__ int g_cnt[NN + 1];
static __device__ int g_start[NN + 1];
static __device__ int g_cursor[NN + 1];
static __device__ int g_eid[EE];
// dst-sorted edge data (built once)
static __device__ __align__(128) int   g_srcs[EE];
static __device__ __align__(128) float g_eas[EE * 10];

// ---------------- helpers ----------------
__device__ __forceinline__ void split_f16(float x, __half& hi, __half& lo) {
    hi = __float2half_rn(x);
    lo = __float2half_rn(x - __half2float(hi));
}

__device__ __forceinline__ uint32_t smem_u32(const void* p) {
    uint32_t a;
    asm("{ .reg .u64 t; cvta.to.shared.u64 t, %1; cvt.u32.u64 %0, t; }" : "=r"(a) : "l"(p));
    return a;
}

__device__ __forceinline__ void cp16(uint32_t dst, const void* src, int bytes) {
    asm volatile("cp.async.cg.shared.global [%0], [%1], 16, %2;"
                 :: "r"(dst), "l"(src), "r"(bytes));
}
__device__ __forceinline__ void cp_commit() {
    asm volatile("cp.async.commit_group;" ::: "memory");
}

__device__ __forceinline__ void mma_f16(float* d, const uint32_t* a, const uint32_t* b) {
    asm volatile(
        "mma.sync.aligned.m16n8k16.row.col.f32.f16.f16.f32 "
        "{%0,%1,%2,%3}, {%4,%5,%6,%7}, {%8,%9}, {%0,%1,%2,%3};"
        : "+f"(d[0]), "+f"(d[1]), "+f"(d[2]), "+f"(d[3])
        : "r"(a[0]), "r"(a[1]), "r"(a[2]), "r"(a[3]), "r"(b[0]), "r"(b[1]));
}

__device__ __forceinline__ void ldsm_x4(uint32_t* r, uint32_t addr) {
    asm volatile("ldmatrix.sync.aligned.m8n8.x4.shared.b16 {%0,%1,%2,%3}, [%4];"
                 : "=r"(r[0]), "=r"(r[1]), "=r"(r[2]), "=r"(r[3]) : "r"(addr));
}
__device__ __forceinline__ void ldsm_x2(uint32_t* r, uint32_t addr) {
    asm volatile("ldmatrix.sync.aligned.m8n8.x2.shared.b16 {%0,%1}, [%2];"
                 : "=r"(r[0]), "=r"(r[1]) : "r"(addr));
}

// ---------------- CSR build ----------------
__global__ void zero_kernel() {
    int i = blockIdx.x * 256 + threadIdx.x;
    if (i <= NN) g_cnt[i] = 0;
}
__global__ void count_kernel(const int* __restrict__ dst) {
    int e = blockIdx.x * 256 + threadIdx.x;
    if (e < EE) atomicAdd(&g_cnt[dst[e]], 1);
}
__global__ void scan_kernel() {
    __shared__ int part[1024];
    const int T = 1024, ITEMS = (NN + T - 1) / T;
    int tid = threadIdx.x, base = tid * ITEMS, s = 0;
    for (int i = 0; i < ITEMS; ++i) { int idx = base + i; if (idx < NN) s += g_cnt[idx]; }
    part[tid] = s;
    __syncthreads();
    for (int off = 1; off < T; off <<= 1) {
        int v = 0;
        if (tid >= off) v = part[tid - off];
        __syncthreads();
        part[tid] += v;
        __syncthreads();
    }
    int run = (tid == 0) ? 0 : part[tid - 1];
    for (int i = 0; i < ITEMS; ++i) {
        int idx = base + i;
        if (idx < NN) { g_start[idx] = run; g_cursor[idx] = run; run += g_cnt[idx]; }
    }
    if (tid == T - 1) g_start[NN] = part[T - 1];
}
__global__ void fill_kernel(const int* __restrict__ dst) {
    int e = blockIdx.x * 256 + threadIdx.x;
    if (e < EE) { int pos = atomicAdd(&g_cursor[dst[e]], 1); g_eid[pos] = e; }
}
// deterministic order: sort each node's list in a local buffer
__global__ void sort_kernel() {
    int n = blockIdx.x * 128 + threadIdx.x;
    if (n >= NN) return;
    int s0 = g_start[n], s1 = g_start[n + 1];
    int d = s1 - s0;
    if (d <= 1) return;
    if (d <= 96) {
        int buf[96];
        for (int i = 0; i < d; ++i) buf[i] = g_eid[s0 + i];
        for (int i = 1; i < d; ++i) {
            int v = buf[i], j = i - 1;
            while (j >= 0 && buf[j] > v) { buf[j + 1] = buf[j]; --j; }
            buf[j + 1] = v;
        }
        for (int i = 0; i < d; ++i) g_eid[s0 + i] = buf[i];
    } else {
        for (int i = s0 + 1; i < s1; ++i) {
            int v = g_eid[i], j = i - 1;
            while (j >= s0 && g_eid[j] > v) { g_eid[j + 1] = g_eid[j]; --j; }
            g_eid[j + 1] = v;
        }
    }
}
// materialize dst-sorted edge arrays (once)
__global__ void gather_kernel(const int* __restrict__ src,
                              const float* __restrict__ eattr) {
    int p = blockIdx.x * 256 + threadIdx.x;
    if (p >= EE) return;
    int e = g_eid[p];
    g_srcs[p] = src[e];
    const float* s = eattr + (size_t)e * 10;
    float* d = g_eas + (size_t)p * 10;
    #pragma unroll
    for (int j = 0; j < 10; ++j) d[j] = s[j];
}

// ---------------- edge-matrix chain precompute ----------------
__global__ void chain_kernel(const float* __restrict__ eW, const float* __restrict__ eb,
                             const float* __restrict__ Weu, const float* __restrict__ beu) {
    __shared__ float Ash[10 * 256];
    __shared__ float dsh[256];
    int tid = threadIdx.x;
    for (int t = tid; t < 2560; t += 256) Ash[t] = eW[t];
    dsh[tid] = eb[tid];
    __syncthreads();
    for (int i = 0; i < NLAY; ++i) {
        for (int t = tid; t < 2560; t += 256) g_A[i * 2560 + t] = Ash[t];
        g_d[i * 256 + tid] = dsh[tid];
        __syncthreads();
        if (i == NLAY - 1) break;
        const float* Wp = Weu + (size_t)i * 65536;
        float accA[10];
        #pragma unroll
        for (int k = 0; k < 10; ++k) accA[k] = 0.f;
        float accd = 0.f;
        for (int c = 0; c < 256; ++c) {
            float w = Wp[c * 256 + tid];
            accd = fmaf(dsh[c], w, accd);
            #pragma unroll
            for (int k = 0; k < 10; ++k) accA[k] = fmaf(Ash[k * 256 + c], w, accA[k]);
        }
        accd += beu[i * 256 + tid];
        __syncthreads();
        #pragma unroll
        for (int k = 0; k < 10; ++k) Ash[k * 256 + tid] = accA[k];
        dsh[tid] = accd;
        __syncthreads();
    }
}
__global__ void bmat_kernel(const float* __restrict__ We) {
    __shared__ float Ash[10 * 256];
    __shared__ float dsh[256];
    int i = blockIdx.x, tid = threadIdx.x;
    for (int t = tid; t < 2560; t += 256) Ash[t] = g_A[i * 2560 + t];
    dsh[tid] = g_d[i * 256 + tid];
    __syncthreads();
    const float* Wp = We + (size_t)i * 65536;
    float accB[10];
    #pragma unroll
    for (int k = 0; k < 10; ++k) accB[k] = 0.f;
    float accc = 0.f;
    for (int c = 0; c < 256; ++c) {
        float w = Wp[c * 256 + tid];
        accc = fmaf(dsh[c], w, accc);
        #pragma unroll
        for (int k = 0; k < 10; ++k) accB[k] = fmaf(Ash[k * 256 + c], w, accB[k]);
    }
    #pragma unroll
    for (int k = 0; k < 10; ++k) g_B[i * 2560 + k * 256 + tid] = accB[k];
    g_c[i * 256 + tid] = accc;
}

// ---------------- weight transpose + fp16 split ----------------
__global__ void wprep_kernel(const float* __restrict__ Wl, const float* __restrict__ Wr,
                             const float* __restrict__ oW1) {
    int idx = blockIdx.x * 256 + threadIdx.x;
    const int LTOT = NLAY * 512 * 256;
    float v;
    if (idx < LTOT) {
        int l = idx >> 17;
        int rem = idx & 131071;
        int row = rem >> 8, k = rem & 255;
        v = (row < 256) ? Wl[(size_t)l * 65536 + k * 256 + row]
                        : Wr[(size_t)l * 65536 + k * 256 + (row - 256)];
    } else if (idx < LTOT + 128 * 256) {
        int rem = idx - LTOT;
        int row = rem >> 8, k = rem & 255;
        v = oW1[k * 128 + row];
    } else return;
    __half hi, lo;
    split_f16(v, hi, lo);
    g_WTh[idx] = hi; g_WTl[idx] = lo;
}

// ---------------- node encoder ----------------
__global__ void encoder_kernel(const float* __restrict__ x, const float* __restrict__ nW,
                               const float* __restrict__ nb) {
    int idx = blockIdx.x * 256 + threadIdx.x;
    int n = idx >> 8, c = idx & 255;
    if (n >= NN) return;
    float s = nb[c];
    #pragma unroll
    for (int k = 0; k < 13; ++k) s = fmaf(x[n * 13 + k], nW[k * 256 + c], s);
    __half hi, lo;
    split_f16(s, hi, lo);
    g_hh[0][idx] = hi; g_hl[0][idx] = lo;
}

// ---------------- FP16 mma.sync GEMM, ldmatrix + cp.async double-buffered ----------------
// xl column blocks (colg<256): 3-pass split (AhBh + AhBl + AlBh) — full fp32-grade.
// xr column blocks: 1-pass AhBh — feeds only attention logits (error budget analysis R7).
#define SA 40
#define ARR_H 5120
#define BUF_H (4 * ARR_H)
#define GSMEM_BYTES (2 * BUF_H * 2)

__global__ __launch_bounds__(256, 2)
void mma_gemm(int hsel, int wrow0, const float* __restrict__ bias0,
              const float* __restrict__ bias1, int outmode, float slope) {
    extern __shared__ __align__(16) __half sm[];
    const __half* __restrict__ Ah = g_hh[hsel];
    const __half* __restrict__ Al = g_hl[hsel];

    int tid = threadIdx.x;
    int wid = tid >> 5, lane = tid & 31;
    int warp_m = wid & 1, warp_n = wid >> 1;
    int m0 = blockIdx.x * 128;
    int colg = blockIdx.y * 128;
    int tig = lane & 3, grp = lane >> 2;
    const bool lo_on = (colg < 256);        // 3-pass for xl + head, 1-pass for xr

    // ldmatrix per-lane address components
    int arow = (lane & 7) + ((lane >> 3) & 1) * 8;  // row within 16-row A tile
    int acol = (lane >> 4) * 8;                     // 0 or 8
    int brow = lane & 7;                            // row within 8-row B tile
    int bcol = ((lane >> 3) & 1) * 8;               // 0 or 8

    float c[4][4][4];
    #pragma unroll
    for (int mi = 0; mi < 4; ++mi)
        #pragma unroll
        for (int ni = 0; ni < 4; ++ni)
            #pragma unroll
            for (int j = 0; j < 4; ++j) c[mi][ni][j] = 0.f;

    auto issue = [&](int kb, int buf) {
        int kt = kb * 32;
        __half* base = sm + buf * BUF_H;
        #pragma unroll
        for (int i = 0; i < 8; ++i) {
            int slot = tid + i * 256;
            int arr = slot >> 9;                  // 0:Ah 1:Al 2:Bh 3:Bl
            if (!lo_on && (arr & 1)) continue;    // xr: skip lo arrays
            int rc = slot & 511;
            int r = rc >> 2, ch = rc & 3;
            const __half* src;
            int bytes = 16;
            if (arr < 2) {
                int gm = m0 + r;
                if (gm >= NN) { gm = NN - 1; bytes = 0; }
                src = (arr == 0 ? Ah : Al) + (size_t)gm * 256 + kt + ch * 8;
            } else {
                int row = wrow0 + colg + r;
                src = (arr == 2 ? g_WTh : g_WTl) + (size_t)row * 256 + kt + ch * 8;
            }
            uint32_t dst = smem_u32(base + arr * ARR_H + r * SA + ch * 8);
            cp16(dst, src, bytes);
        }
        cp_commit();
    };

    issue(0, 0);
    for (int kb = 0; kb < 8; ++kb) {
        if (kb < 7) {
            issue(kb + 1, (kb + 1) & 1);
            asm volatile("cp.async.wait_group 1;" ::: "memory");
        } else {
            asm volatile("cp.async.wait_group 0;" ::: "memory");
        }
        __syncthreads();

        uint32_t sAh = smem_u32(sm + (kb & 1) * BUF_H);
        uint32_t sAl = sAh + ARR_H * 2;
        uint32_t sBh = sAh + 2 * ARR_H * 2;
        uint32_t sBl = sAh + 3 * ARR_H * 2;

        #pragma unroll
        for (int ks = 0; ks < 2; ++ks) {
            int k0 = ks * 16;
            uint32_t bh[4][2], bl[4][2];
            #pragma unroll
            for (int ni = 0; ni < 4; ++ni) {
                uint32_t boff = (uint32_t)((warp_n * 32 + ni * 8 + brow) * SA + k0 + bcol) * 2;
                ldsm_x2(bh[ni], sBh + boff);
                if (lo_on) ldsm_x2(bl[ni], sBl + boff);
            }
            #pragma unroll
            for (int mi = 0; mi < 4; ++mi) {
                uint32_t aoff = (uint32_t)((warp_m * 64 + mi * 16 + arow) * SA + k0 + acol) * 2;
                uint32_t ah[4], al[4];
                ldsm_x4(ah, sAh + aoff);
                if (lo_on) ldsm_x4(al, sAl + aoff);
                #pragma unroll
                for (int ni = 0; ni < 4; ++ni) {
                    mma_f16(c[mi][ni], ah, bh[ni]);
                    if (lo_on) {
                        mma_f16(c[mi][ni], ah, bl[ni]);
                        mma_f16(c[mi][ni], al, bh[ni]);
                    }
                }
            }
        }
        __syncthreads();
    }

    #pragma unroll
    for (int mi = 0; mi < 4; ++mi) {
        #pragma unroll
        for (int ni = 0; ni < 4; ++ni) {
            int gn = colg + warp_n * 32 + ni * 8 + tig * 2;
            float* outp; const float* bp; int cc, ld;
            if (outmode)        { outp = g_t;  bp = bias0; cc = gn;       ld = 128; }
            else if (gn < 256)  { outp = g_xl; bp = bias0; cc = gn;       ld = 256; }
            else                { outp = g_xr; bp = bias1; cc = gn - 256; ld = 256; }
            float b0v = bp[cc], b1v = bp[cc + 1];
            int gm = m0 + warp_m * 64 + mi * 16 + grp;
            if (gm < NN) {
                float v0 = c[mi][ni][0] + b0v; v0 = v0 >= 0.f ? v0 : slope * v0;
                float v1 = c[mi][ni][1] + b1v; v1 = v1 >= 0.f ? v1 : slope * v1;
                *(float2*)(outp + (size_t)gm * ld + cc) = make_float2(v0, v1);
            }
            int gm2 = gm + 8;
            if (gm2 < NN) {
                float v0 = c[mi][ni][2] + b0v; v0 = v0 >= 0.f ? v0 : slope * v0;
                float v1 = c[mi][ni][3] + b1v; v1 = v1 >= 0.f ? v1 : slope * v1;
                *(float2*)(outp + (size_t)gm2 * ld + cc) = make_float2(v0, v1);
            }
        }
    }
}

// ---------------- fused attention: one warp per node, xl touched once ----------------
__global__ __launch_bounds__(128)
void attn_fused(int layer, int hin,
                const float* __restrict__ att, const float* __restrict__ conv_b,
                const float* __restrict__ bng, const float* __restrict__ bnb,
                const float* __restrict__ bnrm, const float* __restrict__ bnrv) {
    int tid = threadIdx.x;
    int warp = tid >> 5, lane = tid & 31;
    int n = blockIdx.x * 4 + warp;
    if (n >= NN) return;
    int hout = hin ^ 1;
    int c0 = lane * 8;

    float Brg[10][8];
    #pragma unroll
    for (int k = 0; k < 10; ++k) {
        float4 b0 = *(const float4*)(g_B + layer * 2560 + k * 256 + c0);
        float4 b1 = *(const float4*)(g_B + layer * 2560 + k * 256 + c0 + 4);
        Brg[k][0] = b0.x; Brg[k][1] = b0.y; Brg[k][2] = b0.z; Brg[k][3] = b0.w;
        Brg[k][4] = b1.x; Brg[k][5] = b1.y; Brg[k][6] = b1.z; Brg[k][7] = b1.w;
    }
    float attr[8], cr[8], xr8[8];
    {
        float4 a0 = *(const float4*)(att + layer * 256 + c0);
        float4 a1 = *(const float4*)(att + layer * 256 + c0 + 4);
        attr[0] = a0.x; attr[1] = a0.y; attr[2] = a0.z; attr[3] = a0.w;
        attr[4] = a1.x; attr[5] = a1.y; attr[6] = a1.z; attr[7] = a1.w;
        float4 d0 = *(const float4*)(g_c + layer * 256 + c0);
        float4 d1 = *(const float4*)(g_c + layer * 256 + c0 + 4);
        cr[0] = d0.x; cr[1] = d0.y; cr[2] = d0.z; cr[3] = d0.w;
        cr[4] = d1.x; cr[5] = d1.y; cr[6] = d1.z; cr[7] = d1.w;
        float4 r0 = *(const float4*)(g_xr + (size_t)n * 256 + c0);
        float4 r1 = *(const float4*)(g_xr + (size_t)n * 256 + c0 + 4);
        xr8[0] = r0.x; xr8[1] = r0.y; xr8[2] = r0.z; xr8[3] = r0.w;
        xr8[4] = r1.x; xr8[5] = r1.y; xr8[6] = r1.z; xr8[7] = r1.w;
    }

    float accv[8];
    #pragma unroll
    for (int j = 0; j < 8; ++j) accv[j] = 0.f;
    float den = 0.f;

    int s0 = g_start[n], s1 = g_start[n + 1];
    for (int p = s0; p < s1; ++p) {
        int sn = g_srcs[p];
        const float2* ea2 = (const float2*)(g_eas + (size_t)p * 10);
        float2 a0 = ea2[0], a1 = ea2[1], a2 = ea2[2], a3 = ea2[3], a4 = ea2[4];
        float ea[10] = {a0.x, a0.y, a1.x, a1.y, a2.x, a2.y, a3.x, a3.y, a4.x, a4.y};

        float4 x0 = *(const float4*)(g_xl + (size_t)sn * 256 + c0);
        float4 x1 = *(const float4*)(g_xl + (size_t)sn * 256 + c0 + 4);
        float xl8[8] = {x0.x, x0.y, x0.z, x0.w, x1.x, x1.y, x1.z, x1.w};

        float m[8];
        #pragma unroll
        for (int j = 0; j < 8; ++j) m[j] = cr[j];
        #pragma unroll
        for (int k = 0; k < 10; ++k)
            #pragma unroll
            for (int j = 0; j < 8; ++j) m[j] = fmaf(ea[k], Brg[k][j], m[j]);

        float s = 0.f;
        #pragma unroll
        for (int j = 0; j < 8; ++j) {
            float v = m[j] + xl8[j] + xr8[j];
            v = v >= 0.f ? v : 0.2f * v;          // leaky 0.2
            s = fmaf(v, attr[j], s);
        }
        s += __shfl_xor_sync(0xffffffffu, s, 1);
        s += __shfl_xor_sync(0xffffffffu, s, 2);
        float w = __expf(s);
        den += w;
        #pragma unroll
        for (int j = 0; j < 8; ++j) accv[j] = fmaf(w, xl8[j], accv[j]);
    }

    float invden = 1.f / (den + 1e-16f);

    float4 cb0 = *(const float4*)(conv_b + layer * 256 + c0);
    float4 cb1 = *(const float4*)(conv_b + layer * 256 + c0 + 4);
    float4 g0  = *(const float4*)(bng + layer * 256 + c0);
    float4 g1  = *(const float4*)(bng + layer * 256 + c0 + 4);
    float4 bb0 = *(const float4*)(bnb + layer * 256 + c0);
    float4 bb1 = *(const float4*)(bnb + layer * 256 + c0 + 4);
    float4 rm0 = *(const float4*)(bnrm + layer * 256 + c0);
    float4 rm1 = *(const float4*)(bnrm + layer * 256 + c0 + 4);
    float4 rv0 = *(const float4*)(bnrv + layer * 256 + c0);
    float4 rv1 = *(const float4*)(bnrv + layer * 256 + c0 + 4);
    float cb[8] = {cb0.x, cb0.y, cb0.z, cb0.w, cb1.x, cb1.y, cb1.z, cb1.w};
    float gg[8] = {g0.x, g0.y, g0.z, g0.w, g1.x, g1.y, g1.z, g1.w};
    float bbv[8] = {bb0.x, bb0.y, bb0.z, bb0.w, bb1.x, bb1.y, bb1.z, bb1.w};
    float rm[8] = {rm0.x, rm0.y, rm0.z, rm0.w, rm1.x, rm1.y, rm1.z, rm1.w};
    float rv[8] = {rv0.x, rv0.y, rv0.z, rv0.w, rv1.x, rv1.y, rv1.z, rv1.w};

    size_t base = (size_t)n * 256 + c0;
    __half resh[8], resl[8];
    if (layer >= 1) {
        *(uint4*)resh = *(const uint4*)(&g_hh[hin][base]);
        *(uint4*)resl = *(const uint4*)(&g_hl[hin][base]);
    }
    __half oh[8], ol[8];
    #pragma unroll
    for (int j = 0; j < 8; ++j) {
        float sc = gg[j] * rsqrtf(rv[j] + 1e-5f);
        float sh = bbv[j] - rm[j] * sc;
        float v = accv[j] * invden + cb[j];
        v = v * sc + sh;
        v = v >= 0.f ? v : 0.01f * v;
        if (layer >= 1) v += __half2float(resh[j]) + __half2float(resl[j]);
        split_f16(v, oh[j], ol[j]);
    }
    *(uint4*)(&g_hh[hout][base]) = *(const uint4*)oh;
    *(uint4*)(&g_hl[hout][base]) = *(const uint4*)ol;
}

// ---------------- head: out = t @ W2 + b2 ----------------
__global__ void head2_kernel(const float* __restrict__ W2, const float* __restrict__ b2,
                             float* __restrict__ out) {
    __shared__ float w[128];
    int tid = threadIdx.x;
    if (tid < 128) w[tid] = W2[tid];
    __syncthreads();
    int n = blockIdx.x * 256 + tid;
    if (n >= NN) return;
    float s = b2[0];
    const float* tp = g_t + (size_t)n * 128;
    #pragma unroll
    for (int j = 0; j < 128; ++j) s = fmaf(tp[j], w[j], s);
    out[n] = s;
}

// ---------------- launch ----------------
extern "C" void kernel_launch(void* const* d_in, const int* in_sizes, int n_in,
                              void* d_out, int out_size) {
    const float* x      = (const float*)d_in[0];
    const int*   ei     = (const int*)d_in[1];
    const float* eattr  = (const float*)d_in[2];
    const float* nW     = (const float*)d_in[3];
    const float* nb     = (const float*)d_in[4];
    const float* eW     = (const float*)d_in[5];
    const float* eb     = (const float*)d_in[6];
    const float* Wl     = (const float*)d_in[7];
    const float* bl     = (const float*)d_in[8];
    const float* Wr     = (const float*)d_in[9];
    const float* br     = (const float*)d_in[10];
    const float* We     = (const float*)d_in[11];
    const float* att    = (const float*)d_in[12];
    const float* conv_b = (const float*)d_in[13];
    const float* Weu    = (const float*)d_in[14];
    const float* beu    = (const float*)d_in[15];
    const float* bng    = (const float*)d_in[16];
    const float* bnb    = (const float*)d_in[17];
    const float* bnrm   = (const float*)d_in[18];
    const float* bnrv   = (const float*)d_in[19];
    const float* oW1    = (const float*)d_in[20];
    const float* ob1    = (const float*)d_in[21];
    const float* oW2    = (const float*)d_in[22];
    const float* ob2    = (const float*)d_in[23];

    const int* srcp = ei;
    const int* dstp = ei + EE;

    static int attr_set = 0;
    if (!attr_set) {
        cudaFuncSetAttribute(mma_gemm, cudaFuncAttributeMaxDynamicSharedMemorySize,
                             GSMEM_BYTES);
        attr_set = 1;
    }

    // CSR build (deterministic) + sorted edge arrays
    zero_kernel<<<(NN + 256) / 256, 256>>>();
    count_kernel<<<(EE + 255) / 256, 256>>>(dstp);
    scan_kernel<<<1, 1024>>>();
    fill_kernel<<<(EE + 255) / 256, 256>>>(dstp);
    sort_kernel<<<(NN + 127) / 128, 128>>>();
    gather_kernel<<<(EE + 255) / 256, 256>>>(srcp, eattr);

    // edge matrix chain + weight prep
    chain_kernel<<<1, 256>>>(eW, eb, Weu, beu);
    bmat_kernel<<<NLAY, 256>>>(We);
    wprep_kernel<<<3200, 256>>>(Wl, Wr, oW1);

    // node encoder
    encoder_kernel<<<NN, 256>>>(x, nW, nb);

    const int MT = (NN + 127) / 128;   // 235
    dim3 gemm_grid(MT, 4);
    dim3 head_grid(MT, 1);
    int cur = 0;
    for (int i = 0; i < NLAY; ++i) {
        mma_gemm<<<gemm_grid, 256, GSMEM_BYTES>>>(cur, i * 512, bl + i * 256, br + i * 256,
                                                  /*outmode=*/0, /*slope=*/1.0f);
        attn_fused<<<(NN + 3) / 4, 128>>>(i, cur, att, conv_b, bng, bnb, bnrm, bnrv);
        cur ^= 1;
    }

    // output head
    mma_gemm<<<head_grid, 256, GSMEM_BYTES>>>(cur, NLAY * 512, ob1, (const float*)0,
                                              /*outmode=*/1, /*slope=*/0.01f);
    head2_kernel<<<(NN + 255) / 256, 256>>>(oW2, ob2, (float*)d_out);
}